// round 1
// baseline (speedup 1.0000x reference)
#include <cuda_runtime.h>

// ---------------------------------------------------------------------------
// T2FN: out = sigmoid( relu( relu( (Σ_t a⊗v⊗x) @ W1 + b1 ) @ W2 + b2 ) @ W3 + b3 )*6 - 3
// a = [1, audio] (49), v = [1, video] (49), x = [1, text] (97)
// fusion index kk = (i*49 + j)*97 + k
//
// Stage 1 (k_build_F): F[b, ij, k] = Σ_t av[b,t,ij] * x[b,t,k]   (per-b GEMM)
// Stage 2 (k_gemm1)  : h1_pre[b,p] += F[b, :] · W1[:, p]          (split-K + atomics)
// Stage 3 (k_tail)   : bias/relu + small MLP + sigmoid
// ---------------------------------------------------------------------------

#define B_    128
#define T_    64
#define ADIM  48
#define VDIM  48
#define XDIM  96
#define PF    128
#define NIJ   2401       // 49*49
#define KX    97         // X+1
#define FDIM  232897     // NIJ*KX

#define KCHUNK 792
#define NSPLIT 296

// Scratch (device globals are the sanctioned way to get scratch memory).
__device__ float g_F[29810816u];       // B_ * FDIM floats = 119.2 MB
__device__ float g_h1pre[B_ * PF];

// ---- packed f32x2 helpers (Blackwell FFMA2 path: 2x fp32 throughput) ------
static __device__ __forceinline__ unsigned long long bcast2(float a) {
    unsigned long long r;
    asm("mov.b64 %0, {%1, %1};" : "=l"(r) : "f"(a));
    return r;
}
static __device__ __forceinline__ unsigned long long ffma2(unsigned long long a,
                                                           unsigned long long b,
                                                           unsigned long long c) {
    unsigned long long d;
    asm("fma.rn.f32x2 %0, %1, %2, %3;" : "=l"(d) : "l"(a), "l"(b), "l"(c));
    return d;
}
static __device__ __forceinline__ void unpack2(unsigned long long v, float& lo, float& hi) {
    asm("mov.b64 {%0, %1}, %2;" : "=f"(lo), "=f"(hi) : "l"(v));
}

// ---------------------------------------------------------------------------
__global__ void k_zero() {
    g_h1pre[blockIdx.x * 256 + threadIdx.x] = 0.f;
}

// ---------------------------------------------------------------------------
// grid (19 ij-blocks, 128 b), block (16,16). Dynamic smem = 64 KB:
//   av[64 t][128 ij]  (t-major, conflict-free broadcast reads)
//   xs[64 t][128 k]   (k padded 97->128 with zeros)
__global__ void k_build_F(const float* __restrict__ audio,
                          const float* __restrict__ video,
                          const float* __restrict__ text) {
    extern __shared__ float sm[];
    float* av = sm;             // 64*128
    float* xs = sm + 64 * 128;  // 64*128

    const int b   = blockIdx.y;
    const int ij0 = blockIdx.x * 128;
    const int tid = threadIdx.y * 16 + threadIdx.x;

    // stage xs (with the "one" at k==0, zero pad k>=97)
    for (int idx = tid; idx < 64 * 128; idx += 256) {
        int t = idx >> 7, k = idx & 127;
        float v = 0.f;
        if (k == 0)      v = 1.f;
        else if (k < KX) v = text[(b * T_ + t) * XDIM + (k - 1)];
        xs[idx] = v;
    }
    // stage av = a_i * v_j (ones at i==0 / j==0), zero for ij >= NIJ
    for (int idx = tid; idx < 64 * 128; idx += 256) {
        int t = idx >> 7, ijl = idx & 127;
        int ij = ij0 + ijl;
        float val = 0.f;
        if (ij < NIJ) {
            int i = ij / 49, j = ij - i * 49;
            float ai = (i == 0) ? 1.f : audio[(b * T_ + t) * ADIM + (i - 1)];
            float vj = (j == 0) ? 1.f : video[(b * T_ + t) * VDIM + (j - 1)];
            val = ai * vj;
        }
        av[t * 128 + ijl] = val;
    }
    __syncthreads();

    unsigned long long acc[8][4];
#pragma unroll
    for (int m = 0; m < 8; m++)
#pragma unroll
        for (int n = 0; n < 4; n++) acc[m][n] = 0ull;

    const int mbase = threadIdx.y * 8;   // ij tile
    const int kbase = threadIdx.x * 8;   // k tile (4 f32x2 pairs)

#pragma unroll 2
    for (int t = 0; t < 64; t++) {
        const float4* ap = reinterpret_cast<const float4*>(av + t * 128 + mbase);
        float4 A0 = ap[0], A1 = ap[1];
        const unsigned long long* xp =
            reinterpret_cast<const unsigned long long*>(xs + t * 128 + kbase);
        unsigned long long X0 = xp[0], X1 = xp[1], X2 = xp[2], X3 = xp[3];
        float am[8] = {A0.x, A0.y, A0.z, A0.w, A1.x, A1.y, A1.z, A1.w};
#pragma unroll
        for (int m = 0; m < 8; m++) {
            unsigned long long a2 = bcast2(am[m]);
            acc[m][0] = ffma2(a2, X0, acc[m][0]);
            acc[m][1] = ffma2(a2, X1, acc[m][1]);
            acc[m][2] = ffma2(a2, X2, acc[m][2]);
            acc[m][3] = ffma2(a2, X3, acc[m][3]);
        }
    }

#pragma unroll
    for (int m = 0; m < 8; m++) {
        int ij = ij0 + mbase + m;
        if (ij >= NIJ) continue;
        unsigned int base = (unsigned int)b * FDIM + (unsigned int)ij * KX;
#pragma unroll
        for (int n = 0; n < 4; n++) {
            float lo, hi;
            unpack2(acc[m][n], lo, hi);
            int k = kbase + 2 * n;
            if (k < KX)     g_F[base + k]     = lo;
            if (k + 1 < KX) g_F[base + k + 1] = hi;
        }
    }
}

// ---------------------------------------------------------------------------
// Split-K GEMM: h1_pre[128,128] += F[128, kchunk] @ W1[kchunk, 128]
// grid NSPLIT, block (16,16), 8x8 register tiles, f32x2 FMAs, fp32 atomics.
__global__ void k_gemm1(const float* __restrict__ W1) {
    const int kstart = blockIdx.x * KCHUNK;
    if (kstart >= FDIM) return;
    const int kend = (kstart + KCHUNK < FDIM) ? kstart + KCHUNK : FDIM;

    __shared__ float As[8][132];   // [k][b], padded
    __shared__ float Bs[8][128];   // [k][p]

    const int tid = threadIdx.y * 16 + threadIdx.x;

    unsigned long long acc[8][4];
#pragma unroll
    for (int m = 0; m < 8; m++)
#pragma unroll
        for (int n = 0; n < 4; n++) acc[m][n] = 0ull;

    const int mbase = threadIdx.y * 8;   // b tile
    const int nbase = threadIdx.x * 8;   // p tile

    const int arow  = tid >> 1;          // b: 0..127
    const int ahalf = (tid & 1) * 4;     // k offset within 8
    const int brow  = tid >> 5;          // k row: 0..7
    const int bcol  = (tid * 4) & 127;   // p: 0..124 step 4

    for (int kk0 = kstart; kk0 < kend; kk0 += 8) {
        // A tile: F[arow][kk0 + ahalf + i], zero-fill past kend
#pragma unroll
        for (int i2 = 0; i2 < 4; i2++) {
            int kk = kk0 + ahalf + i2;
            float v = (kk < kend) ? g_F[(unsigned int)arow * FDIM + kk] : 0.f;
            As[ahalf + i2][arow] = v;
        }
        // B tile: W1[kk][p], coalesced float4
        {
            int kk = kk0 + brow;
            float4 v = make_float4(0.f, 0.f, 0.f, 0.f);
            if (kk < kend)
                v = *reinterpret_cast<const float4*>(W1 + (unsigned int)kk * PF + bcol);
            *reinterpret_cast<float4*>(&Bs[brow][bcol]) = v;
        }
        __syncthreads();

#pragma unroll
        for (int kt = 0; kt < 8; kt++) {
            const float4* ap = reinterpret_cast<const float4*>(&As[kt][mbase]);
            float4 A0 = ap[0], A1 = ap[1];
            const unsigned long long* bp =
                reinterpret_cast<const unsigned long long*>(&Bs[kt][nbase]);
            unsigned long long X0 = bp[0], X1 = bp[1], X2 = bp[2], X3 = bp[3];
            float am[8] = {A0.x, A0.y, A0.z, A0.w, A1.x, A1.y, A1.z, A1.w};
#pragma unroll
            for (int m = 0; m < 8; m++) {
                unsigned long long a2 = bcast2(am[m]);
                acc[m][0] = ffma2(a2, X0, acc[m][0]);
                acc[m][1] = ffma2(a2, X1, acc[m][1]);
                acc[m][2] = ffma2(a2, X2, acc[m][2]);
                acc[m][3] = ffma2(a2, X3, acc[m][3]);
            }
        }
        __syncthreads();
    }

#pragma unroll
    for (int m = 0; m < 8; m++) {
        int brow_out = mbase + m;
#pragma unroll
        for (int n = 0; n < 4; n++) {
            float lo, hi;
            unpack2(acc[m][n], lo, hi);
            int p = nbase + 2 * n;
            atomicAdd(&g_h1pre[brow_out * PF + p],     lo);
            atomicAdd(&g_h1pre[brow_out * PF + p + 1], hi);
        }
    }
}

// ---------------------------------------------------------------------------
// Tail MLP: one CTA per batch row.
__global__ void k_tail(const float* __restrict__ b1, const float* __restrict__ W2,
                       const float* __restrict__ b2, const float* __restrict__ W3,
                       const float* __restrict__ b3, float* __restrict__ out) {
    __shared__ float h1s[PF];
    __shared__ float red[PF];
    const int b = blockIdx.x;
    const int q = threadIdx.x;

    float h1 = g_h1pre[b * PF + q] + b1[q];
    h1s[q] = fmaxf(h1, 0.f);
    __syncthreads();

    float acc = b2[q];
#pragma unroll 8
    for (int p = 0; p < PF; p++) acc = fmaf(h1s[p], W2[p * PF + q], acc);
    float h2 = fmaxf(acc, 0.f);

    red[q] = h2 * W3[q];
    __syncthreads();
    for (int s = 64; s > 0; s >>= 1) {
        if (q < s) red[q] += red[q + s];
        __syncthreads();
    }
    if (q == 0) {
        float z = red[0] + b3[0];
        out[b] = 6.f / (1.f + expf(-z)) - 3.f;
    }
}

// ---------------------------------------------------------------------------
extern "C" void kernel_launch(void* const* d_in, const int* in_sizes, int n_in,
                              void* d_out, int out_size) {
    const float* audio = (const float*)d_in[0];
    const float* video = (const float*)d_in[1];
    const float* text  = (const float*)d_in[2];
    const float* W1    = (const float*)d_in[3];
    const float* b1    = (const float*)d_in[4];
    const float* W2    = (const float*)d_in[5];
    const float* b2    = (const float*)d_in[6];
    const float* W3    = (const float*)d_in[7];
    const float* b3    = (const float*)d_in[8];
    float* out = (float*)d_out;

    cudaFuncSetAttribute(k_build_F, cudaFuncAttributeMaxDynamicSharedMemorySize, 65536);

    k_zero<<<64, 256>>>();
    k_build_F<<<dim3(19, 128), dim3(16, 16), 65536>>>(audio, video, text);
    k_gemm1<<<NSPLIT, dim3(16, 16)>>>(W1);
    k_tail<<<128, 128>>>(b1, W2, b2, W3, b3, out);
}

// round 5
// speedup vs baseline: 1.3582x; 1.3582x over previous
#include <cuda_runtime.h>
#include <cuda_bf16.h>
#include <cstdint>

// ---------------------------------------------------------------------------
// T2FN on GB300 (base sm_103 target -> mma.sync HMMA, no tcgen05):
//  Stage 1 (k_build_F): F[b,ij,k] = sum_t (a_i v_j)(x_k), packed bf16 hi/lo u32
//  Stage 2 (k_gemm_mma): h1_pre = F @ W1, bf16-split 3-combo mma.sync,
//                        split-K over 296 CTAs -> per-CTA partials
//  Stage 3 (k_finish):   reduce partials + bias/relu + MLP + sigmoid
// ---------------------------------------------------------------------------

#define B_    128
#define T_    64
#define ADIM  48
#define VDIM  48
#define XDIM  96
#define PF    128
#define NIJ   2401       // 49*49
#define KX    97         // X+1
#define FDIM  232897     // NIJ*KX
#define FDIMP 232900u    // padded row stride (multiple of 4)
#define KC    64         // K per chunk
#define NCHUNK 3640      // ceil(FDIM/64)
#define NSPLIT 296       // split-K CTAs (2 per SM)

// scratch
__device__ uint32_t g_F2[(size_t)B_ * FDIMP];   // packed (bf16 hi | bf16 lo<<16)
__device__ float    g_part[(size_t)NSPLIT * B_ * PF];

// ---- fp32x2 helpers (stage 1) ---------------------------------------------
static __device__ __forceinline__ unsigned long long bcast2(float a) {
    unsigned long long r; asm("mov.b64 %0, {%1, %1};" : "=l"(r) : "f"(a)); return r;
}
static __device__ __forceinline__ unsigned long long ffma2(unsigned long long a,
                                                           unsigned long long b,
                                                           unsigned long long c) {
    unsigned long long d;
    asm("fma.rn.f32x2 %0, %1, %2, %3;" : "=l"(d) : "l"(a), "l"(b), "l"(c));
    return d;
}
static __device__ __forceinline__ void unpack2(unsigned long long v, float& lo, float& hi) {
    asm("mov.b64 {%0, %1}, %2;" : "=f"(lo), "=f"(hi) : "l"(v));
}
static __device__ __forceinline__ uint32_t pack_hilo(float f) {
    __nv_bfloat16 h = __float2bfloat16(f);
    float r = f - __bfloat162float(h);
    __nv_bfloat16 l = __float2bfloat16(r);
    return (uint32_t)__bfloat16_as_ushort(h) | ((uint32_t)__bfloat16_as_ushort(l) << 16);
}

// ---- mma.sync bf16 (m16n8k16) ---------------------------------------------
static __device__ __forceinline__ void mma_bf16(float* d, const uint32_t* a,
                                                const uint32_t* b) {
    asm volatile(
        "mma.sync.aligned.m16n8k16.row.col.f32.bf16.bf16.f32 "
        "{%0,%1,%2,%3}, {%4,%5,%6,%7}, {%8,%9}, {%0,%1,%2,%3};"
        : "+f"(d[0]), "+f"(d[1]), "+f"(d[2]), "+f"(d[3])
        : "r"(a[0]), "r"(a[1]), "r"(a[2]), "r"(a[3]), "r"(b[0]), "r"(b[1]));
}

// ---------------------------------------------------------------------------
// Stage 1: per-b GEMM F_b = AV_b[128ij x 64t] @ X_b[64t x 97k], fp32, write
// packed bf16 hi/lo. grid (19, 128), block (16,16), 64KB dyn smem.
__global__ void k_build_F(const float* __restrict__ audio,
                          const float* __restrict__ video,
                          const float* __restrict__ text) {
    extern __shared__ float sm[];
    float* av = sm;             // [64 t][128 ij]
    float* xs = sm + 64 * 128;  // [64 t][128 k] (k padded)

    const int b   = blockIdx.y;
    const int ij0 = blockIdx.x * 128;
    const int tid = threadIdx.y * 16 + threadIdx.x;

    for (int idx = tid; idx < 64 * 128; idx += 256) {
        int t = idx >> 7, k = idx & 127;
        float v = 0.f;
        if (k == 0)      v = 1.f;
        else if (k < KX) v = text[(b * T_ + t) * XDIM + (k - 1)];
        xs[idx] = v;
    }
    for (int idx = tid; idx < 64 * 128; idx += 256) {
        int t = idx >> 7, ijl = idx & 127;
        int ij = ij0 + ijl;
        float val = 0.f;
        if (ij < NIJ) {
            int i = ij / 49, j = ij - i * 49;
            float ai = (i == 0) ? 1.f : audio[(b * T_ + t) * ADIM + (i - 1)];
            float vj = (j == 0) ? 1.f : video[(b * T_ + t) * VDIM + (j - 1)];
            val = ai * vj;
        }
        av[t * 128 + ijl] = val;
    }
    __syncthreads();

    unsigned long long acc[8][4];
#pragma unroll
    for (int m = 0; m < 8; m++)
#pragma unroll
        for (int n = 0; n < 4; n++) acc[m][n] = 0ull;

    const int mbase = threadIdx.y * 8;
    const int kbase = threadIdx.x * 8;

#pragma unroll 2
    for (int t = 0; t < 64; t++) {
        const float4* ap = reinterpret_cast<const float4*>(av + t * 128 + mbase);
        float4 A0 = ap[0], A1 = ap[1];
        const unsigned long long* xp =
            reinterpret_cast<const unsigned long long*>(xs + t * 128 + kbase);
        unsigned long long X0 = xp[0], X1 = xp[1], X2 = xp[2], X3 = xp[3];
        float am[8] = {A0.x, A0.y, A0.z, A0.w, A1.x, A1.y, A1.z, A1.w};
#pragma unroll
        for (int m = 0; m < 8; m++) {
            unsigned long long a2 = bcast2(am[m]);
            acc[m][0] = ffma2(a2, X0, acc[m][0]);
            acc[m][1] = ffma2(a2, X1, acc[m][1]);
            acc[m][2] = ffma2(a2, X2, acc[m][2]);
            acc[m][3] = ffma2(a2, X3, acc[m][3]);
        }
    }

#pragma unroll
    for (int m = 0; m < 8; m++) {
        int ij = ij0 + mbase + m;
        if (ij >= NIJ) continue;
        uint32_t base = (uint32_t)b * FDIMP + (uint32_t)ij * KX;
#pragma unroll
        for (int n = 0; n < 4; n++) {
            float lo, hi;
            unpack2(acc[m][n], lo, hi);
            int k = kbase + 2 * n;
            if (k < KX)     g_F2[base + k]     = pack_hilo(lo);
            if (k + 1 < KX) g_F2[base + k + 1] = pack_hilo(hi);
        }
    }
}

// ---------------------------------------------------------------------------
// Stage 2: split-K HMMA GEMM. grid NSPLIT, block 256 (8 warps, 2m x 4n).
// SMEM (word-granularity layouts, conflict-free fragment loads):
//   As: packed u32 [128 m][64 k], row stride 72 words (288B = 18*16B)
//   Bs: packed u32 [64 k][128 p], row stride 132 words (528B)
static constexpr int SA_STRIDE = 72;    // words
static constexpr int SB_STRIDE = 132;   // words
static constexpr int S_B_OFF   = 128 * SA_STRIDE;           // word offset
static constexpr int S_WORDS   = S_B_OFF + KC * SB_STRIDE;  // 9216 + 8448
static constexpr int S_BYTES   = S_WORDS * 4;               // 70656 B

__global__ __launch_bounds__(256, 2)
void k_gemm_mma(const float* __restrict__ W1) {
    extern __shared__ uint32_t smw[];
    uint32_t* As = smw;
    uint32_t* Bs = smw + S_B_OFF;

    const int tid = threadIdx.x;
    const int wid = tid >> 5;
    const int lid = tid & 31;
    const int g   = lid >> 2;       // 0..7
    const int tg  = lid & 3;        // 0..3
    const int mbase = (wid >> 2) * 64;   // 0 or 64
    const int nbase = (wid & 3) * 32;    // 0,32,64,96

    float acc[4][4][4];
#pragma unroll
    for (int mt = 0; mt < 4; mt++)
#pragma unroll
        for (int nt = 0; nt < 4; nt++)
#pragma unroll
            for (int r = 0; r < 4; r++) acc[mt][nt][r] = 0.f;

    for (int c = blockIdx.x; c < NCHUNK; c += NSPLIT) {
        const uint32_t kk0 = (uint32_t)c * KC;
        const bool full = (kk0 + KC <= FDIM);
        __syncthreads();   // previous compute done before restage

        // ---- A stage: raw u32 copy of packed F chunk ----
        // 128 rows x 16 uint4-slots = 2048 slots, 256 threads -> 8 iterations
#pragma unroll 4
        for (int it = 0; it < 8; it++) {
            int idx = it * 256 + tid;
            int row = idx >> 4;              // 0..127
            int q4  = (idx & 15) * 4;        // 0..60
            uint4 v;
            if (full) {
                v = *reinterpret_cast<const uint4*>(
                    &g_F2[(size_t)row * FDIMP + kk0 + q4]);
            } else {
                const size_t base = (size_t)row * FDIMP + kk0 + q4;
                v.x = (kk0 + q4 + 0 < FDIM) ? g_F2[base + 0] : 0u;
                v.y = (kk0 + q4 + 1 < FDIM) ? g_F2[base + 1] : 0u;
                v.z = (kk0 + q4 + 2 < FDIM) ? g_F2[base + 2] : 0u;
                v.w = (kk0 + q4 + 3 < FDIM) ? g_F2[base + 3] : 0u;
            }
            *reinterpret_cast<uint4*>(&As[row * SA_STRIDE + q4]) = v;
        }

        // ---- B stage: W1 fp32 -> packed hi/lo u32, [k][p] ----
#pragma unroll 2
        for (int it = 0; it < 8; it++) {
            int kr = it * 8 + (tid >> 5);    // 0..63
            int pl = (tid & 31) * 4;         // 0..124
            uint32_t gk = kk0 + (uint32_t)kr;
            float4 w = make_float4(0.f, 0.f, 0.f, 0.f);
            if (gk < FDIM)
                w = *reinterpret_cast<const float4*>(&W1[(size_t)gk * PF + pl]);
            uint4 pv;
            pv.x = pack_hilo(w.x); pv.y = pack_hilo(w.y);
            pv.z = pack_hilo(w.z); pv.w = pack_hilo(w.w);
            *reinterpret_cast<uint4*>(&Bs[kr * SB_STRIDE + pl]) = pv;
        }
        __syncthreads();

        // ---- compute: 4 k16-steps ----
#pragma unroll
        for (int k0 = 0; k0 < KC; k0 += 16) {
            // b fragments for 4 n-tiles
            uint32_t bh[4][2], bl[4][2];
#pragma unroll
            for (int nt = 0; nt < 4; nt++) {
                const uint32_t* col = &Bs[(k0 + 2 * tg) * SB_STRIDE + nbase + nt * 8 + g];
                uint32_t w0 = col[0];
                uint32_t w1 = col[SB_STRIDE];
                uint32_t w2 = col[8 * SB_STRIDE];
                uint32_t w3 = col[9 * SB_STRIDE];
                bh[nt][0] = __byte_perm(w0, w1, 0x5410);
                bl[nt][0] = __byte_perm(w0, w1, 0x7632);
                bh[nt][1] = __byte_perm(w2, w3, 0x5410);
                bl[nt][1] = __byte_perm(w2, w3, 0x7632);
            }
#pragma unroll
            for (int mt = 0; mt < 4; mt++) {
                const int r = mbase + mt * 16 + g;
                uint2 q0 = *reinterpret_cast<const uint2*>(&As[r * SA_STRIDE + k0 + 2 * tg]);
                uint2 q1 = *reinterpret_cast<const uint2*>(&As[(r + 8) * SA_STRIDE + k0 + 2 * tg]);
                uint2 q2 = *reinterpret_cast<const uint2*>(&As[r * SA_STRIDE + k0 + 2 * tg + 8]);
                uint2 q3 = *reinterpret_cast<const uint2*>(&As[(r + 8) * SA_STRIDE + k0 + 2 * tg + 8]);
                uint32_t ah[4], al[4];
                ah[0] = __byte_perm(q0.x, q0.y, 0x5410); al[0] = __byte_perm(q0.x, q0.y, 0x7632);
                ah[1] = __byte_perm(q1.x, q1.y, 0x5410); al[1] = __byte_perm(q1.x, q1.y, 0x7632);
                ah[2] = __byte_perm(q2.x, q2.y, 0x5410); al[2] = __byte_perm(q2.x, q2.y, 0x7632);
                ah[3] = __byte_perm(q3.x, q3.y, 0x5410); al[3] = __byte_perm(q3.x, q3.y, 0x7632);
#pragma unroll
                for (int nt = 0; nt < 4; nt++) {
                    mma_bf16(acc[mt][nt], ah, bh[nt]);   // hi*hi
                    mma_bf16(acc[mt][nt], ah, bl[nt]);   // hi*lo
                    mma_bf16(acc[mt][nt], al, bh[nt]);   // lo*hi
                }
            }
        }
    }

    // ---- epilogue: write per-CTA partial ----
    float* part = &g_part[(size_t)blockIdx.x * (B_ * PF)];
#pragma unroll
    for (int mt = 0; mt < 4; mt++) {
        int row = mbase + mt * 16 + g;
#pragma unroll
        for (int nt = 0; nt < 4; nt++) {
            int col = nbase + nt * 8 + 2 * tg;
            *reinterpret_cast<float2*>(&part[(size_t)row * PF + col]) =
                make_float2(acc[mt][nt][0], acc[mt][nt][1]);
            *reinterpret_cast<float2*>(&part[(size_t)(row + 8) * PF + col]) =
                make_float2(acc[mt][nt][2], acc[mt][nt][3]);
        }
    }
}

// ---------------------------------------------------------------------------
// Stage 3: reduce split-K partials + MLP tail. grid 128 (b), block 128 (q).
__global__ void k_finish(const float* __restrict__ b1, const float* __restrict__ W2,
                         const float* __restrict__ b2, const float* __restrict__ W3,
                         const float* __restrict__ b3, float* __restrict__ out) {
    __shared__ float h1s[PF];
    __shared__ float red[PF];
    const int b = blockIdx.x;
    const int q = threadIdx.x;

    float s0 = 0.f, s1 = 0.f, s2 = 0.f, s3 = 0.f;
    const size_t off = (size_t)b * PF + q;
#pragma unroll 4
    for (int c = 0; c < NSPLIT; c += 4) {
        s0 += g_part[(size_t)(c + 0) * (B_ * PF) + off];
        s1 += g_part[(size_t)(c + 1) * (B_ * PF) + off];
        s2 += g_part[(size_t)(c + 2) * (B_ * PF) + off];
        s3 += g_part[(size_t)(c + 3) * (B_ * PF) + off];
    }
    float h1 = (s0 + s1) + (s2 + s3) + b1[q];
    h1s[q] = fmaxf(h1, 0.f);
    __syncthreads();

    float a0 = b2[q], a1 = 0.f, a2 = 0.f, a3 = 0.f;
#pragma unroll 8
    for (int p = 0; p < PF; p += 4) {
        a0 = fmaf(h1s[p + 0], W2[(p + 0) * PF + q], a0);
        a1 = fmaf(h1s[p + 1], W2[(p + 1) * PF + q], a1);
        a2 = fmaf(h1s[p + 2], W2[(p + 2) * PF + q], a2);
        a3 = fmaf(h1s[p + 3], W2[(p + 3) * PF + q], a3);
    }
    float h2 = fmaxf((a0 + a1) + (a2 + a3), 0.f);

    red[q] = h2 * W3[q];
    __syncthreads();
    for (int s = 64; s > 0; s >>= 1) {
        if (q < s) red[q] += red[q + s];
        __syncthreads();
    }
    if (q == 0) {
        float z = red[0] + b3[0];
        out[b] = 6.f / (1.f + expf(-z)) - 3.f;
    }
}

// ---------------------------------------------------------------------------
extern "C" void kernel_launch(void* const* d_in, const int* in_sizes, int n_in,
                              void* d_out, int out_size) {
    const float* audio = (const float*)d_in[0];
    const float* video = (const float*)d_in[1];
    const float* text  = (const float*)d_in[2];
    const float* W1    = (const float*)d_in[3];
    const float* b1    = (const float*)d_in[4];
    const float* W2    = (const float*)d_in[5];
    const float* b2    = (const float*)d_in[6];
    const float* W3    = (const float*)d_in[7];
    const float* b3    = (const float*)d_in[8];
    float* out = (float*)d_out;

    cudaFuncSetAttribute(k_build_F, cudaFuncAttributeMaxDynamicSharedMemorySize, 65536);
    cudaFuncSetAttribute(k_gemm_mma, cudaFuncAttributeMaxDynamicSharedMemorySize, S_BYTES);

    k_build_F<<<dim3(19, 128), dim3(16, 16), 65536>>>(audio, video, text);
    k_gemm_mma<<<NSPLIT, 256, S_BYTES>>>(W1);
    k_finish<<<128, 128>>>(b1, W2, b2, W3, b3, out);
}

// round 7
// speedup vs baseline: 2.0713x; 1.5250x over previous
#include <cuda_runtime.h>
#include <cuda_bf16.h>
#include <cstdint>

// ---------------------------------------------------------------------------
// T2FN on GB300 (base sm_103 target -> mma.sync HMMA):
//  Stage 1 (k_build_F_mma): per-b GEMM AV[128ij x 64t] @ X[64t x 97k] via
//                           bf16-split 3-combo mma.sync -> packed F
//  Stage 2 (k_gemm_mma):    h1_pre = F @ W1, same scheme, split-K 296 CTAs
//  Stage 3 (k_finish):      reduce partials + bias/relu + MLP + sigmoid
// ---------------------------------------------------------------------------

#define B_    128
#define T_    64
#define ADIM  48
#define VDIM  48
#define XDIM  96
#define PF    128
#define NIJ   2401       // 49*49
#define KX    97         // X+1
#define FDIM  232897     // NIJ*KX
#define FDIMP 232900u    // padded row stride (multiple of 4)
#define KC    64         // K per chunk
#define NCHUNK 3640      // ceil(FDIM/64)
#define NSPLIT 296       // split-K CTAs (2 per SM)

// scratch
__device__ uint32_t g_F2[(size_t)B_ * FDIMP];   // packed (bf16 hi | bf16 lo<<16)
__device__ float    g_part[(size_t)NSPLIT * B_ * PF];

static __device__ __forceinline__ uint32_t pack_hilo(float f) {
    __nv_bfloat16 h = __float2bfloat16(f);
    float r = f - __bfloat162float(h);
    __nv_bfloat16 l = __float2bfloat16(r);
    return (uint32_t)__bfloat16_as_ushort(h) | ((uint32_t)__bfloat16_as_ushort(l) << 16);
}

// ---- mma.sync bf16 (m16n8k16) ---------------------------------------------
static __device__ __forceinline__ void mma_bf16(float* d, const uint32_t* a,
                                                const uint32_t* b) {
    asm volatile(
        "mma.sync.aligned.m16n8k16.row.col.f32.bf16.bf16.f32 "
        "{%0,%1,%2,%3}, {%4,%5,%6,%7}, {%8,%9}, {%0,%1,%2,%3};"
        : "+f"(d[0]), "+f"(d[1]), "+f"(d[2]), "+f"(d[3])
        : "r"(a[0]), "r"(a[1]), "r"(a[2]), "r"(a[3]), "r"(b[0]), "r"(b[1]));
}

// shared strides (words) — same conflict-free layout in both GEMM kernels
static constexpr int SA_STRIDE = 72;    // [row][64 k] pad to 72
static constexpr int SB_STRIDE = 132;   // [k][128 n] pad to 132

// ---------------------------------------------------------------------------
// Stage 1: grid (19 ij-tiles, 128 b), block 256 (8 warps, 2m x 4n).
// SMEM: As u32[128][72] (AV packed), Xs u32[64][132] (X packed),
//       aud f32[64][49], vid f32[64][49]
static constexpr int S1_XS_OFF  = 128 * SA_STRIDE;                 // words
static constexpr int S1_AUD_OFF = S1_XS_OFF + KC * SB_STRIDE;      // words
static constexpr int S1_VID_OFF = S1_AUD_OFF + 64 * 49;
static constexpr int S1_WORDS   = S1_VID_OFF + 64 * 49;
static constexpr int S1_BYTES   = S1_WORDS * 4;                    // 95744

__global__ __launch_bounds__(256, 2)
void k_build_F_mma(const float* __restrict__ audio,
                   const float* __restrict__ video,
                   const float* __restrict__ text) {
    extern __shared__ uint32_t smw[];
    uint32_t* As = smw;
    uint32_t* Xs = smw + S1_XS_OFF;
    float*    aud = reinterpret_cast<float*>(smw + S1_AUD_OFF);
    float*    vid = reinterpret_cast<float*>(smw + S1_VID_OFF);

    const int b   = blockIdx.y;
    const int ij0 = blockIdx.x * 128;
    const int tid = threadIdx.x;
    const int wid = tid >> 5;
    const int lid = tid & 31;
    const int g   = lid >> 2;            // 0..7
    const int tg  = lid & 3;             // 0..3
    const int mbase = (wid >> 2) * 64;   // 0 or 64
    const int nbase = (wid & 3) * 32;    // 0,32,64,96

    // stage audio/video rows for this b (coalesced; stride-49 pad -> no bank conflicts)
#pragma unroll 3
    for (int idx = tid; idx < T_ * ADIM; idx += 256) {
        int t = idx / ADIM, c = idx - t * ADIM;
        aud[t * 49 + c] = audio[(size_t)b * (T_ * ADIM) + idx];
        vid[t * 49 + c] = video[(size_t)b * (T_ * ADIM) + idx];
    }
    // stage X packed: [t][n], n==0 -> 1, 1..96 -> text, pad -> 0
#pragma unroll 4
    for (int idx = tid; idx < T_ * 128; idx += 256) {
        int t = idx >> 7, n = idx & 127;
        float v = 0.f;
        if (n == 0)      v = 1.f;
        else if (n < KX) v = text[((size_t)b * T_ + t) * XDIM + (n - 1)];
        Xs[t * SB_STRIDE + n] = pack_hilo(v);
    }
    __syncthreads();

    // compute AV packed: As[ijl][t]; per-thread fixed t, ijl steps by 4
    {
        const int t = tid & 63;
        const int r0 = tid >> 6;         // 0..3
#pragma unroll 4
        for (int it = 0; it < 32; it++) {
            int ijl = it * 4 + r0;
            int ij  = ij0 + ijl;
            float val = 0.f;
            if (ij < NIJ) {
                int i = ij / 49;
                int j = ij - i * 49;
                float ai = i ? aud[t * 49 + (i - 1)] : 1.f;
                float vj = j ? vid[t * 49 + (j - 1)] : 1.f;
                val = ai * vj;
            }
            As[ijl * SA_STRIDE + t] = pack_hilo(val);
        }
    }
    __syncthreads();

    // ---- 3-combo HMMA over K=64 (t) ----
    float acc[4][4][4];
#pragma unroll
    for (int mt = 0; mt < 4; mt++)
#pragma unroll
        for (int nt = 0; nt < 4; nt++)
#pragma unroll
            for (int r = 0; r < 4; r++) acc[mt][nt][r] = 0.f;

#pragma unroll
    for (int k0 = 0; k0 < KC; k0 += 16) {
        uint32_t bh[4][2], bl[4][2];
#pragma unroll
        for (int nt = 0; nt < 4; nt++) {
            const uint32_t* col = &Xs[(k0 + 2 * tg) * SB_STRIDE + nbase + nt * 8 + g];
            uint32_t w0 = col[0];
            uint32_t w1 = col[SB_STRIDE];
            uint32_t w2 = col[8 * SB_STRIDE];
            uint32_t w3 = col[9 * SB_STRIDE];
            bh[nt][0] = __byte_perm(w0, w1, 0x5410);
            bl[nt][0] = __byte_perm(w0, w1, 0x7632);
            bh[nt][1] = __byte_perm(w2, w3, 0x5410);
            bl[nt][1] = __byte_perm(w2, w3, 0x7632);
        }
#pragma unroll
        for (int mt = 0; mt < 4; mt++) {
            const int r = mbase + mt * 16 + g;
            uint2 q0 = *reinterpret_cast<const uint2*>(&As[r * SA_STRIDE + k0 + 2 * tg]);
            uint2 q1 = *reinterpret_cast<const uint2*>(&As[(r + 8) * SA_STRIDE + k0 + 2 * tg]);
            uint2 q2 = *reinterpret_cast<const uint2*>(&As[r * SA_STRIDE + k0 + 2 * tg + 8]);
            uint2 q3 = *reinterpret_cast<const uint2*>(&As[(r + 8) * SA_STRIDE + k0 + 2 * tg + 8]);
            uint32_t ah[4], al[4];
            ah[0] = __byte_perm(q0.x, q0.y, 0x5410); al[0] = __byte_perm(q0.x, q0.y, 0x7632);
            ah[1] = __byte_perm(q1.x, q1.y, 0x5410); al[1] = __byte_perm(q1.x, q1.y, 0x7632);
            ah[2] = __byte_perm(q2.x, q2.y, 0x5410); al[2] = __byte_perm(q2.x, q2.y, 0x7632);
            ah[3] = __byte_perm(q3.x, q3.y, 0x5410); al[3] = __byte_perm(q3.x, q3.y, 0x7632);
#pragma unroll
            for (int nt = 0; nt < 4; nt++) {
                mma_bf16(acc[mt][nt], ah, bh[nt]);   // hi*hi
                mma_bf16(acc[mt][nt], ah, bl[nt]);   // hi*lo
                mma_bf16(acc[mt][nt], al, bh[nt]);   // lo*hi
            }
        }
    }

    // ---- epilogue: pack to bf16 hi/lo and store F ----
#pragma unroll
    for (int mt = 0; mt < 4; mt++) {
        int row  = mbase + mt * 16 + g;
        int ija  = ij0 + row;
        int ijb  = ija + 8;
        size_t basea = (size_t)b * FDIMP + (size_t)ija * KX;
        size_t baseb = (size_t)b * FDIMP + (size_t)ijb * KX;
#pragma unroll
        for (int nt = 0; nt < 4; nt++) {
            int col = nbase + nt * 8 + 2 * tg;
            if (ija < NIJ) {
                if (col < KX)     g_F2[basea + col]     = pack_hilo(acc[mt][nt][0]);
                if (col + 1 < KX) g_F2[basea + col + 1] = pack_hilo(acc[mt][nt][1]);
            }
            if (ijb < NIJ) {
                if (col < KX)     g_F2[baseb + col]     = pack_hilo(acc[mt][nt][2]);
                if (col + 1 < KX) g_F2[baseb + col + 1] = pack_hilo(acc[mt][nt][3]);
            }
        }
    }
}

// ---------------------------------------------------------------------------
// Stage 2: split-K HMMA GEMM. grid NSPLIT, block 256 (8 warps, 2m x 4n).
static constexpr int S_B_OFF   = 128 * SA_STRIDE;           // word offset
static constexpr int S_WORDS   = S_B_OFF + KC * SB_STRIDE;
static constexpr int S_BYTES   = S_WORDS * 4;               // 70656 B

__global__ __launch_bounds__(256, 2)
void k_gemm_mma(const float* __restrict__ W1) {
    extern __shared__ uint32_t smw[];
    uint32_t* As = smw;
    uint32_t* Bs = smw + S_B_OFF;

    const int tid = threadIdx.x;
    const int wid = tid >> 5;
    const int lid = tid & 31;
    const int g   = lid >> 2;
    const int tg  = lid & 3;
    const int mbase = (wid >> 2) * 64;
    const int nbase = (wid & 3) * 32;

    float acc[4][4][4];
#pragma unroll
    for (int mt = 0; mt < 4; mt++)
#pragma unroll
        for (int nt = 0; nt < 4; nt++)
#pragma unroll
            for (int r = 0; r < 4; r++) acc[mt][nt][r] = 0.f;

    for (int c = blockIdx.x; c < NCHUNK; c += NSPLIT) {
        const uint32_t kk0 = (uint32_t)c * KC;
        const bool full = (kk0 + KC <= FDIM);
        __syncthreads();

        // A stage: raw u32 copy of packed F chunk (128 rows x 16 uint4 = 2048 slots)
#pragma unroll 4
        for (int it = 0; it < 8; it++) {
            int idx = it * 256 + tid;
            int row = idx >> 4;
            int q4  = (idx & 15) * 4;
            uint4 v;
            if (full) {
                v = *reinterpret_cast<const uint4*>(&g_F2[(size_t)row * FDIMP + kk0 + q4]);
            } else {
                const size_t base = (size_t)row * FDIMP + kk0 + q4;
                v.x = (kk0 + q4 + 0 < FDIM) ? g_F2[base + 0] : 0u;
                v.y = (kk0 + q4 + 1 < FDIM) ? g_F2[base + 1] : 0u;
                v.z = (kk0 + q4 + 2 < FDIM) ? g_F2[base + 2] : 0u;
                v.w = (kk0 + q4 + 3 < FDIM) ? g_F2[base + 3] : 0u;
            }
            *reinterpret_cast<uint4*>(&As[row * SA_STRIDE + q4]) = v;
        }

        // B stage: W1 fp32 -> packed hi/lo u32, [k][p]
#pragma unroll 2
        for (int it = 0; it < 8; it++) {
            int kr = it * 8 + (tid >> 5);
            int pl = (tid & 31) * 4;
            uint32_t gk = kk0 + (uint32_t)kr;
            float4 w = make_float4(0.f, 0.f, 0.f, 0.f);
            if (gk < FDIM)
                w = *reinterpret_cast<const float4*>(&W1[(size_t)gk * PF + pl]);
            uint4 pv;
            pv.x = pack_hilo(w.x); pv.y = pack_hilo(w.y);
            pv.z = pack_hilo(w.z); pv.w = pack_hilo(w.w);
            *reinterpret_cast<uint4*>(&Bs[kr * SB_STRIDE + pl]) = pv;
        }
        __syncthreads();

#pragma unroll
        for (int k0 = 0; k0 < KC; k0 += 16) {
            uint32_t bh[4][2], bl[4][2];
#pragma unroll
            for (int nt = 0; nt < 4; nt++) {
                const uint32_t* col = &Bs[(k0 + 2 * tg) * SB_STRIDE + nbase + nt * 8 + g];
                uint32_t w0 = col[0];
                uint32_t w1 = col[SB_STRIDE];
                uint32_t w2 = col[8 * SB_STRIDE];
                uint32_t w3 = col[9 * SB_STRIDE];
                bh[nt][0] = __byte_perm(w0, w1, 0x5410);
                bl[nt][0] = __byte_perm(w0, w1, 0x7632);
                bh[nt][1] = __byte_perm(w2, w3, 0x5410);
                bl[nt][1] = __byte_perm(w2, w3, 0x7632);
            }
#pragma unroll
            for (int mt = 0; mt < 4; mt++) {
                const int r = mbase + mt * 16 + g;
                uint2 q0 = *reinterpret_cast<const uint2*>(&As[r * SA_STRIDE + k0 + 2 * tg]);
                uint2 q1 = *reinterpret_cast<const uint2*>(&As[(r + 8) * SA_STRIDE + k0 + 2 * tg]);
                uint2 q2 = *reinterpret_cast<const uint2*>(&As[r * SA_STRIDE + k0 + 2 * tg + 8]);
                uint2 q3 = *reinterpret_cast<const uint2*>(&As[(r + 8) * SA_STRIDE + k0 + 2 * tg + 8]);
                uint32_t ah[4], al[4];
                ah[0] = __byte_perm(q0.x, q0.y, 0x5410); al[0] = __byte_perm(q0.x, q0.y, 0x7632);
                ah[1] = __byte_perm(q1.x, q1.y, 0x5410); al[1] = __byte_perm(q1.x, q1.y, 0x7632);
                ah[2] = __byte_perm(q2.x, q2.y, 0x5410); al[2] = __byte_perm(q2.x, q2.y, 0x7632);
                ah[3] = __byte_perm(q3.x, q3.y, 0x5410); al[3] = __byte_perm(q3.x, q3.y, 0x7632);
#pragma unroll
                for (int nt = 0; nt < 4; nt++) {
                    mma_bf16(acc[mt][nt], ah, bh[nt]);
                    mma_bf16(acc[mt][nt], ah, bl[nt]);
                    mma_bf16(acc[mt][nt], al, bh[nt]);
                }
            }
        }
    }

    float* part = &g_part[(size_t)blockIdx.x * (B_ * PF)];
#pragma unroll
    for (int mt = 0; mt < 4; mt++) {
        int row = mbase + mt * 16 + g;
#pragma unroll
        for (int nt = 0; nt < 4; nt++) {
            int col = nbase + nt * 8 + 2 * tg;
            *reinterpret_cast<float2*>(&part[(size_t)row * PF + col]) =
                make_float2(acc[mt][nt][0], acc[mt][nt][1]);
            *reinterpret_cast<float2*>(&part[(size_t)(row + 8) * PF + col]) =
                make_float2(acc[mt][nt][2], acc[mt][nt][3]);
        }
    }
}

// ---------------------------------------------------------------------------
// Stage 3: reduce split-K partials + MLP tail. grid 128 (b), block 128 (q).
__global__ void k_finish(const float* __restrict__ b1, const float* __restrict__ W2,
                         const float* __restrict__ b2, const float* __restrict__ W3,
                         const float* __restrict__ b3, float* __restrict__ out) {
    __shared__ float h1s[PF];
    __shared__ float red[PF];
    const int b = blockIdx.x;
    const int q = threadIdx.x;

    float s0 = 0.f, s1 = 0.f, s2 = 0.f, s3 = 0.f;
    const size_t off = (size_t)b * PF + q;
#pragma unroll 4
    for (int c = 0; c < NSPLIT; c += 4) {
        s0 += g_part[(size_t)(c + 0) * (B_ * PF) + off];
        s1 += g_part[(size_t)(c + 1) * (B_ * PF) + off];
        s2 += g_part[(size_t)(c + 2) * (B_ * PF) + off];
        s3 += g_part[(size_t)(c + 3) * (B_ * PF) + off];
    }
    float h1 = (s0 + s1) + (s2 + s3) + b1[q];
    h1s[q] = fmaxf(h1, 0.f);
    __syncthreads();

    float a0 = b2[q], a1 = 0.f, a2 = 0.f, a3 = 0.f;
#pragma unroll 8
    for (int p = 0; p < PF; p += 4) {
        a0 = fmaf(h1s[p + 0], W2[(p + 0) * PF + q], a0);
        a1 = fmaf(h1s[p + 1], W2[(p + 1) * PF + q], a1);
        a2 = fmaf(h1s[p + 2], W2[(p + 2) * PF + q], a2);
        a3 = fmaf(h1s[p + 3], W2[(p + 3) * PF + q], a3);
    }
    float h2 = fmaxf((a0 + a1) + (a2 + a3), 0.f);

    red[q] = h2 * W3[q];
    __syncthreads();
    for (int s = 64; s > 0; s >>= 1) {
        if (q < s) red[q] += red[q + s];
        __syncthreads();
    }
    if (q == 0) {
        float z = red[0] + b3[0];
        out[b] = 6.f / (1.f + expf(-z)) - 3.f;
    }
}

// ---------------------------------------------------------------------------
extern "C" void kernel_launch(void* const* d_in, const int* in_sizes, int n_in,
                              void* d_out, int out_size) {
    const float* audio = (const float*)d_in[0];
    const float* video = (const float*)d_in[1];
    const float* text  = (const float*)d_in[2];
    const float* W1    = (const float*)d_in[3];
    const float* b1    = (const float*)d_in[4];
    const float* W2    = (const float*)d_in[5];
    const float* b2    = (const float*)d_in[6];
    const float* W3    = (const float*)d_in[7];
    const float* b3    = (const float*)d_in[8];
    float* out = (float*)d_out;

    cudaFuncSetAttribute(k_build_F_mma, cudaFuncAttributeMaxDynamicSharedMemorySize, S1_BYTES);
    cudaFuncSetAttribute(k_gemm_mma,   cudaFuncAttributeMaxDynamicSharedMemorySize, S_BYTES);

    k_build_F_mma<<<dim3(19, 128), 256, S1_BYTES>>>(audio, video, text);
    k_gemm_mma<<<NSPLIT, 256, S_BYTES>>>(W1);
    k_finish<<<128, 128>>>(b1, W2, b2, W3, b3, out);
}

// round 8
// speedup vs baseline: 2.3492x; 1.1341x over previous
#include <cuda_runtime.h>
#include <cuda_bf16.h>
#include <cstdint>

// ---------------------------------------------------------------------------
// T2FN on GB300 — hi/lo bf16 plane design (no perms anywhere):
//  Stage 1 (k_build_F): per-b HMMA GEMM AV[128ij x 64t] @ X[64t x 97k] ->
//                       F stored as two gmem planes (bf16x2 pairs, 98-padded)
//  Stage 2 (k_gemm_mma): h1_pre = F @ W1, split-K 296 CTAs, 3-combo HMMA
//  Stage 3 (k_finish):   reduce partials + bias/relu + MLP + sigmoid
// ---------------------------------------------------------------------------

#define B_    128
#define T_    64
#define ADIM  48
#define XDIM  96
#define PF    128
#define NIJ   2401        // 49*49
#define KX    97          // X+1
#define KXP   98          // padded per-ij k (even)
#define FDIM2 235298      // NIJ*KXP (flat padded K)
#define NPAIR 117649      // NIJ*49 valid pairs per b
#define KPC   32          // pairs per chunk (64 flat k)
#define NCHUNK2 3677      // ceil(NPAIR/32)
#define FROWP 117664u     // padded pairs per b row (3677*32)
#define NSPLIT 296

// F planes: u32 = bf16x2 of (flat k even, odd). Pad region stays 0 (never written).
__device__ uint32_t g_Fhi[(size_t)B_ * FROWP];
__device__ uint32_t g_Flo[(size_t)B_ * FROWP];
__device__ float    g_part[(size_t)NSPLIT * B_ * PF];

// pack two fp32 -> bf16x2 hi plane word + lo (residual) plane word
static __device__ __forceinline__ void cvt2(float v0, float v1, uint32_t& h, uint32_t& l) {
    uint32_t hh;
    asm("cvt.rn.bf16x2.f32 %0, %1, %2;" : "=r"(hh) : "f"(v1), "f"(v0));
    float h0 = __uint_as_float(hh << 16);
    float h1 = __uint_as_float(hh & 0xFFFF0000u);
    float r0 = v0 - h0, r1 = v1 - h1;
    asm("cvt.rn.bf16x2.f32 %0, %1, %2;" : "=r"(l) : "f"(r1), "f"(r0));
    h = hh;
}

static __device__ __forceinline__ void mma_bf16(float* d, const uint32_t* a,
                                                const uint32_t* b) {
    asm volatile(
        "mma.sync.aligned.m16n8k16.row.col.f32.bf16.bf16.f32 "
        "{%0,%1,%2,%3}, {%4,%5,%6,%7}, {%8,%9}, {%0,%1,%2,%3};"
        : "+f"(d[0]), "+f"(d[1]), "+f"(d[2]), "+f"(d[3])
        : "r"(a[0]), "r"(a[1]), "r"(a[2]), "r"(a[3]), "r"(b[0]), "r"(b[1]));
}

static constexpr int PSTR = 36;   // plane row stride in words (32 pairs + pad)

// ---------------------------------------------------------------------------
// Stage 1. grid (19 ij-tiles, 128 b), block 256 (8 warps, 2m x 4n).
static constexpr int S1_AHI = 0;
static constexpr int S1_ALO = 128 * PSTR;            // 4608
static constexpr int S1_XHI = 2 * 128 * PSTR;        // 9216
static constexpr int S1_XLO = 3 * 128 * PSTR;        // 13824
static constexpr int S1_AUD = 4 * 128 * PSTR;        // 18432
static constexpr int S1_VID = S1_AUD + T_ * 49;      // 21568
static constexpr int S1_WORDS = S1_VID + T_ * 49;    // 24704
static constexpr int S1_BYTES = S1_WORDS * 4;        // 98816

__global__ __launch_bounds__(256, 2)
void k_build_F(const float* __restrict__ audio,
               const float* __restrict__ video,
               const float* __restrict__ text) {
    extern __shared__ uint32_t smw[];
    uint32_t* Ahi = smw + S1_AHI;
    uint32_t* Alo = smw + S1_ALO;
    uint32_t* Xhi = smw + S1_XHI;
    uint32_t* Xlo = smw + S1_XLO;
    float*    aud = reinterpret_cast<float*>(smw + S1_AUD);
    float*    vid = reinterpret_cast<float*>(smw + S1_VID);

    const int b   = blockIdx.y;
    const int ij0 = blockIdx.x * 128;
    const int tid = threadIdx.x;
    const int wid = tid >> 5;
    const int lid = tid & 31;
    const int g   = lid >> 2;
    const int tg  = lid & 3;
    const int mbase = (wid >> 2) * 64;
    const int nbase = (wid & 3) * 32;

    // stage audio/video (coalesced reads; stride-49 rows)
#pragma unroll 3
    for (int idx = tid; idx < T_ * ADIM; idx += 256) {
        int t = idx / ADIM, c = idx - t * ADIM;
        aud[t * 49 + c] = audio[(size_t)b * (T_ * ADIM) + idx];
        vid[t * 49 + c] = video[(size_t)b * (T_ * ADIM) + idx];
    }

    // stage X planes: [n][tpair], word-swizzled by (n>>3)&3
#pragma unroll
    for (int it = 0; it < 16; it++) {
        int tp = it * 2 + (tid >> 7);       // 0..31
        int n  = tid & 127;
        int t0 = 2 * tp;
        float v0 = 0.f, v1 = 0.f;
        if (n == 0) { v0 = 1.f; v1 = 1.f; }
        else if (n < KX) {
            const float* tx = &text[((size_t)b * T_ + t0) * XDIM + (n - 1)];
            v0 = tx[0];
            v1 = tx[XDIM];
        }
        uint32_t h, l;
        cvt2(v0, v1, h, l);
        int col = tp ^ ((n >> 3) & 3);
        Xhi[n * PSTR + col] = h;
        Xlo[n * PSTR + col] = l;
    }
    __syncthreads();

    // compute AV planes: [ijl][tpair], no swizzle
    {
        const int tp = tid & 31;            // t-pair
        const int r0 = tid >> 5;            // 0..7
        const int t0 = 2 * tp;
#pragma unroll 4
        for (int it = 0; it < 16; it++) {
            int ijl = it * 8 + r0;
            int ij  = ij0 + ijl;
            float v0 = 0.f, v1 = 0.f;
            if (ij < NIJ) {
                int i = ij / 49;
                int j = ij - i * 49;
                float a0 = i ? aud[t0 * 49 + (i - 1)] : 1.f;
                float a1 = i ? aud[(t0 + 1) * 49 + (i - 1)] : 1.f;
                float w0 = j ? vid[t0 * 49 + (j - 1)] : 1.f;
                float w1 = j ? vid[(t0 + 1) * 49 + (j - 1)] : 1.f;
                v0 = a0 * w0;
                v1 = a1 * w1;
            }
            uint32_t h, l;
            cvt2(v0, v1, h, l);
            Ahi[ijl * PSTR + tp] = h;
            Alo[ijl * PSTR + tp] = l;
        }
    }
    __syncthreads();

    // ---- 3-combo HMMA over K=64 (t): 4 ksteps ----
    float acc[4][4][4];
#pragma unroll
    for (int mt = 0; mt < 4; mt++)
#pragma unroll
        for (int nt = 0; nt < 4; nt++)
#pragma unroll
            for (int r = 0; r < 4; r++) acc[mt][nt][r] = 0.f;

#pragma unroll
    for (int ks = 0; ks < 4; ks++) {
        const int kp0 = ks * 8;
        uint32_t bh[4][2], bl[4][2];
#pragma unroll
        for (int nt = 0; nt < 4; nt++) {
            int n  = nbase + nt * 8 + g;
            int cB = (n >> 3) & 3;
            const uint32_t* ph = &Xhi[n * PSTR + kp0 + (tg ^ cB)];
            const uint32_t* pl = &Xlo[n * PSTR + kp0 + (tg ^ cB)];
            bh[nt][0] = ph[0]; bh[nt][1] = ph[4];
            bl[nt][0] = pl[0]; bl[nt][1] = pl[4];
        }
#pragma unroll
        for (int mt = 0; mt < 4; mt++) {
            const int r = mbase + mt * 16 + g;
            const uint32_t* ph = &Ahi[r * PSTR + kp0 + tg];
            const uint32_t* pl = &Alo[r * PSTR + kp0 + tg];
            uint32_t ah[4], al[4];
            ah[0] = ph[0]; ah[1] = ph[8 * PSTR]; ah[2] = ph[4]; ah[3] = ph[8 * PSTR + 4];
            al[0] = pl[0]; al[1] = pl[8 * PSTR]; al[2] = pl[4]; al[3] = pl[8 * PSTR + 4];
#pragma unroll
            for (int nt = 0; nt < 4; nt++) {
                mma_bf16(acc[mt][nt], ah, bh[nt]);
                mma_bf16(acc[mt][nt], ah, bl[nt]);
                mma_bf16(acc[mt][nt], al, bh[nt]);
            }
        }
    }

    // ---- epilogue: split result pairs into gmem planes ----
#pragma unroll
    for (int mt = 0; mt < 4; mt++) {
        int row = mbase + mt * 16 + g;
        int ija = ij0 + row;
        int ijb = ija + 8;
#pragma unroll
        for (int nt = 0; nt < 4; nt++) {
            int col = nbase + nt * 8 + 2 * tg;         // even
            if (col > 96) continue;                     // cols 0..96 live (97 is pad=0)
            int pr = col >> 1;                          // pair index within ij
            if (ija < NIJ) {
                size_t o = (size_t)b * FROWP + (size_t)ija * 49 + pr;
                uint32_t h, l;
                cvt2(acc[mt][nt][0], acc[mt][nt][1], h, l);
                g_Fhi[o] = h; g_Flo[o] = l;
            }
            if (ijb < NIJ) {
                size_t o = (size_t)b * FROWP + (size_t)ijb * 49 + pr;
                uint32_t h, l;
                cvt2(acc[mt][nt][2], acc[mt][nt][3], h, l);
                g_Fhi[o] = h; g_Flo[o] = l;
            }
        }
    }
}

// ---------------------------------------------------------------------------
// Stage 2: split-K HMMA GEMM over padded flat K. grid NSPLIT, block 256.
static constexpr int S2_AHI = 0;
static constexpr int S2_ALO = 128 * PSTR;
static constexpr int S2_BHI = 2 * 128 * PSTR;
static constexpr int S2_BLO = 3 * 128 * PSTR;
static constexpr int S2_WORDS = 4 * 128 * PSTR;   // 18432
static constexpr int S2_BYTES = S2_WORDS * 4;     // 73728

__global__ __launch_bounds__(256, 2)
void k_gemm_mma(const float* __restrict__ W1) {
    extern __shared__ uint32_t smw[];
    uint32_t* Ahi = smw + S2_AHI;
    uint32_t* Alo = smw + S2_ALO;
    uint32_t* Bhi = smw + S2_BHI;
    uint32_t* Blo = smw + S2_BLO;

    const int tid = threadIdx.x;
    const int wid = tid >> 5;
    const int lid = tid & 31;
    const int g   = lid >> 2;
    const int tg  = lid & 3;
    const int mbase = (wid >> 2) * 64;
    const int nbase = (wid & 3) * 32;

    float acc[4][4][4];
#pragma unroll
    for (int mt = 0; mt < 4; mt++)
#pragma unroll
        for (int nt = 0; nt < 4; nt++)
#pragma unroll
            for (int r = 0; r < 4; r++) acc[mt][nt][r] = 0.f;

    for (int c = blockIdx.x; c < NCHUNK2; c += NSPLIT) {
        const uint32_t kp_base = (uint32_t)c * KPC;   // pair offset, always in-bounds (FROWP pad)
        __syncthreads();

        // ---- A stage: raw uint4 copies (128 rows x 8 uint4 per plane) ----
#pragma unroll
        for (int it = 0; it < 4; it++) {
            int idx = it * 256 + tid;
            int row = idx >> 3;
            int q4  = (idx & 7) * 4;
            uint4 v = *reinterpret_cast<const uint4*>(&g_Fhi[(size_t)row * FROWP + kp_base + q4]);
            *reinterpret_cast<uint4*>(&Ahi[row * PSTR + q4]) = v;
        }
#pragma unroll
        for (int it = 0; it < 4; it++) {
            int idx = it * 256 + tid;
            int row = idx >> 3;
            int q4  = (idx & 7) * 4;
            uint4 v = *reinterpret_cast<const uint4*>(&g_Flo[(size_t)row * FROWP + kp_base + q4]);
            *reinterpret_cast<uint4*>(&Alo[row * PSTR + q4]) = v;
        }

        // ---- B stage: W1 (98-pad remap) -> planes [p][kpair] swizzled ----
#pragma unroll
        for (int it = 0; it < 16; it++) {
            int kp = it * 2 + (tid >> 7);    // 0..31
            int p  = tid & 127;
            uint32_t gk0 = (kp_base + kp) * 2;
            uint32_t gk1 = gk0 + 1;
            uint32_t ij0q = gk0 / KXP, cc0 = gk0 - ij0q * KXP;
            uint32_t ij1q = gk1 / KXP, cc1 = gk1 - ij1q * KXP;
            float w0 = 0.f, w1 = 0.f;
            if (ij0q < NIJ && cc0 < KX)
                w0 = W1[(size_t)(gk0 - ij0q) * PF + p];
            if (ij1q < NIJ && cc1 < KX)
                w1 = W1[(size_t)(gk1 - ij1q) * PF + p];
            uint32_t h, l;
            cvt2(w0, w1, h, l);
            int col = kp ^ ((p >> 3) & 3);
            Bhi[p * PSTR + col] = h;
            Blo[p * PSTR + col] = l;
        }
        __syncthreads();

        // ---- compute: 4 ksteps x 3 combos ----
#pragma unroll
        for (int ks = 0; ks < 4; ks++) {
            const int kp0 = ks * 8;
            uint32_t bh[4][2], bl[4][2];
#pragma unroll
            for (int nt = 0; nt < 4; nt++) {
                int n  = nbase + nt * 8 + g;
                int cB = (n >> 3) & 3;
                const uint32_t* ph = &Bhi[n * PSTR + kp0 + (tg ^ cB)];
                const uint32_t* pl = &Blo[n * PSTR + kp0 + (tg ^ cB)];
                bh[nt][0] = ph[0]; bh[nt][1] = ph[4];
                bl[nt][0] = pl[0]; bl[nt][1] = pl[4];
            }
#pragma unroll
            for (int mt = 0; mt < 4; mt++) {
                const int r = mbase + mt * 16 + g;
                const uint32_t* ph = &Ahi[r * PSTR + kp0 + tg];
                const uint32_t* pl = &Alo[r * PSTR + kp0 + tg];
                uint32_t ah[4], al[4];
                ah[0] = ph[0]; ah[1] = ph[8 * PSTR]; ah[2] = ph[4]; ah[3] = ph[8 * PSTR + 4];
                al[0] = pl[0]; al[1] = pl[8 * PSTR]; al[2] = pl[4]; al[3] = pl[8 * PSTR + 4];
#pragma unroll
                for (int nt = 0; nt < 4; nt++) {
                    mma_bf16(acc[mt][nt], ah, bh[nt]);
                    mma_bf16(acc[mt][nt], ah, bl[nt]);
                    mma_bf16(acc[mt][nt], al, bh[nt]);
                }
            }
        }
    }

    float* part = &g_part[(size_t)blockIdx.x * (B_ * PF)];
#pragma unroll
    for (int mt = 0; mt < 4; mt++) {
        int row = mbase + mt * 16 + g;
#pragma unroll
        for (int nt = 0; nt < 4; nt++) {
            int col = nbase + nt * 8 + 2 * tg;
            *reinterpret_cast<float2*>(&part[(size_t)row * PF + col]) =
                make_float2(acc[mt][nt][0], acc[mt][nt][1]);
            *reinterpret_cast<float2*>(&part[(size_t)(row + 8) * PF + col]) =
                make_float2(acc[mt][nt][2], acc[mt][nt][3]);
        }
    }
}

// ---------------------------------------------------------------------------
// Stage 3: reduce split-K partials + MLP tail. grid 128 (b), block 128 (q).
__global__ void k_finish(const float* __restrict__ b1, const float* __restrict__ W2,
                         const float* __restrict__ b2, const float* __restrict__ W3,
                         const float* __restrict__ b3, float* __restrict__ out) {
    __shared__ float h1s[PF];
    __shared__ float red[PF];
    const int b = blockIdx.x;
    const int q = threadIdx.x;

    float s0 = 0.f, s1 = 0.f, s2 = 0.f, s3 = 0.f;
    const size_t off = (size_t)b * PF + q;
#pragma unroll 4
    for (int c = 0; c < NSPLIT; c += 4) {
        s0 += g_part[(size_t)(c + 0) * (B_ * PF) + off];
        s1 += g_part[(size_t)(c + 1) * (B_ * PF) + off];
        s2 += g_part[(size_t)(c + 2) * (B_ * PF) + off];
        s3 += g_part[(size_t)(c + 3) * (B_ * PF) + off];
    }
    float h1 = (s0 + s1) + (s2 + s3) + b1[q];
    h1s[q] = fmaxf(h1, 0.f);
    __syncthreads();

    float a0 = b2[q], a1 = 0.f, a2 = 0.f, a3 = 0.f;
#pragma unroll 8
    for (int p = 0; p < PF; p += 4) {
        a0 = fmaf(h1s[p + 0], W2[(p + 0) * PF + q], a0);
        a1 = fmaf(h1s[p + 1], W2[(p + 1) * PF + q], a1);
        a2 = fmaf(h1s[p + 2], W2[(p + 2) * PF + q], a2);
        a3 = fmaf(h1s[p + 3], W2[(p + 3) * PF + q], a3);
    }
    float h2 = fmaxf((a0 + a1) + (a2 + a3), 0.f);

    red[q] = h2 * W3[q];
    __syncthreads();
    for (int s = 64; s > 0; s >>= 1) {
        if (q < s) red[q] += red[q + s];
        __syncthreads();
    }
    if (q == 0) {
        float z = red[0] + b3[0];
        out[b] = 6.f / (1.f + expf(-z)) - 3.f;
    }
}

// ---------------------------------------------------------------------------
extern "C" void kernel_launch(void* const* d_in, const int* in_sizes, int n_in,
                              void* d_out, int out_size) {
    const float* audio = (const float*)d_in[0];
    const float* video = (const float*)d_in[1];
    const float* text  = (const float*)d_in[2];
    const float* W1    = (const float*)d_in[3];
    const float* b1    = (const float*)d_in[4];
    const float* W2    = (const float*)d_in[5];
    const float* b2    = (const float*)d_in[6];
    const float* W3    = (const float*)d_in[7];
    const float* b3    = (const float*)d_in[8];
    float* out = (float*)d_out;

    cudaFuncSetAttribute(k_build_F, cudaFuncAttributeMaxDynamicSharedMemorySize, S1_BYTES);
    cudaFuncSetAttribute(k_gemm_mma, cudaFuncAttributeMaxDynamicSharedMemorySize, S2_BYTES);

    k_build_F<<<dim3(19, 128), 256, S1_BYTES>>>(audio, video, text);
    k_gemm_mma<<<NSPLIT, 256, S2_BYTES>>>(W1);
    k_finish<<<128, 128>>>(b1, W2, b2, W3, b3, out);
}

// round 9
// speedup vs baseline: 2.7595x; 1.1747x over previous
#include <cuda_runtime.h>
#include <cuda_bf16.h>
#include <cstdint>

// ---------------------------------------------------------------------------
// T2FN on GB300 — hi/lo bf16 plane design, amortized staging + coalesced F IO:
//  Stage 1 (k_build_F): per-b persistent CTA (half the ij-tiles), HMMA GEMM,
//                       coalesced two-pass epilogue through smem
//  Stage 2 (k_gemm_mma): h1_pre = F @ W1, split-K, cp.async A prefetch,
//                        cheap B index math
//  Stage 3 (k_finish):   reduce partials + MLP tail
// ---------------------------------------------------------------------------

#define B_    128
#define T_    64
#define ADIM  48
#define XDIM  96
#define PF    128
#define NIJ   2401        // 49*49
#define KX    97          // X+1
#define KXP   98
#define NPAIR 117649      // NIJ*49
#define KPC   32          // pairs per chunk
#define NCHUNK2 3677
#define FROWP 117664u     // padded pairs per b
#define NSPLIT 296

__device__ uint32_t g_Fhi[(size_t)B_ * FROWP];
__device__ uint32_t g_Flo[(size_t)B_ * FROWP];
__device__ float    g_part[(size_t)NSPLIT * B_ * PF];

static __device__ __forceinline__ uint32_t cvthi(float v0, float v1) {
    uint32_t h;
    asm("cvt.rn.bf16x2.f32 %0, %1, %2;" : "=r"(h) : "f"(v1), "f"(v0));
    return h;
}
static __device__ __forceinline__ void cvt2(float v0, float v1, uint32_t& h, uint32_t& l) {
    uint32_t hh = cvthi(v0, v1);
    float h0 = __uint_as_float(hh << 16);
    float h1 = __uint_as_float(hh & 0xFFFF0000u);
    float r0 = v0 - h0, r1 = v1 - h1;
    asm("cvt.rn.bf16x2.f32 %0, %1, %2;" : "=r"(l) : "f"(r1), "f"(r0));
    h = hh;
}
static __device__ __forceinline__ uint32_t smem_u32(const void* p) {
    uint32_t a;
    asm("{ .reg .u64 t; cvta.to.shared.u64 t, %1; cvt.u32.u64 %0, t; }" : "=r"(a) : "l"(p));
    return a;
}
#define CPA16(dst, src) \
    asm volatile("cp.async.cg.shared.global [%0], [%1], 16;" :: "r"(dst), "l"(src))

static __device__ __forceinline__ void mma_bf16(float* d, const uint32_t* a,
                                                const uint32_t* b) {
    asm volatile(
        "mma.sync.aligned.m16n8k16.row.col.f32.bf16.bf16.f32 "
        "{%0,%1,%2,%3}, {%4,%5,%6,%7}, {%8,%9}, {%0,%1,%2,%3};"
        : "+f"(d[0]), "+f"(d[1]), "+f"(d[2]), "+f"(d[3])
        : "r"(a[0]), "r"(a[1]), "r"(a[2]), "r"(a[3]), "r"(b[0]), "r"(b[1]));
}

static constexpr int PSTR = 36;   // plane row stride (words)

// ---------------------------------------------------------------------------
// Stage 1 smem (words):
//   [0..9215]      Ahi[128][36] @0, Alo @4608; epilogue staging overlays @0 (6272 w)
//   [9216..18431]  Xhi @9216, Xlo @13824
//   [18432..]      aud (64*49), vid
static constexpr int S1_ALO = 4608;
static constexpr int S1_XHI = 9216;
static constexpr int S1_XLO = 13824;
static constexpr int S1_AUD = 18432;
static constexpr int S1_VID = S1_AUD + T_ * 49;
static constexpr int S1_WORDS = S1_VID + T_ * 49;   // 24704
static constexpr int S1_BYTES = S1_WORDS * 4;       // 98816

__global__ __launch_bounds__(256, 2)
void k_build_F(const float* __restrict__ audio,
               const float* __restrict__ video,
               const float* __restrict__ text) {
    extern __shared__ uint32_t smw[];
    uint32_t* Ahi = smw;
    uint32_t* Alo = smw + S1_ALO;
    uint32_t* Xhi = smw + S1_XHI;
    uint32_t* Xlo = smw + S1_XLO;
    uint32_t* stg = smw;                 // epilogue staging overlay (6272 words)
    float* aud = reinterpret_cast<float*>(smw + S1_AUD);
    float* vid = reinterpret_cast<float*>(smw + S1_VID);

    const int b     = blockIdx.y;
    const int tstart = blockIdx.x ? 10 : 0;
    const int tend   = blockIdx.x ? 19 : 10;
    const int tid = threadIdx.x;
    const int wid = tid >> 5;
    const int lid = tid & 31;
    const int g   = lid >> 2;
    const int tg  = lid & 3;
    const int mbase = (wid >> 2) * 64;
    const int nbase = (wid & 3) * 32;

    // ---- one-time staging: aud/vid + X planes ----
#pragma unroll 3
    for (int idx = tid; idx < T_ * ADIM; idx += 256) {
        int t = idx / ADIM, c = idx - t * ADIM;
        aud[t * 49 + c] = audio[(size_t)b * (T_ * ADIM) + idx];
        vid[t * 49 + c] = video[(size_t)b * (T_ * ADIM) + idx];
    }
#pragma unroll
    for (int it = 0; it < 16; it++) {
        int tp = it * 2 + (tid >> 7);
        int n  = tid & 127;
        int t0 = 2 * tp;
        float v0 = 0.f, v1 = 0.f;
        if (n == 0) { v0 = 1.f; v1 = 1.f; }
        else if (n < KX) {
            const float* tx = &text[((size_t)b * T_ + t0) * XDIM + (n - 1)];
            v0 = tx[0];
            v1 = tx[XDIM];
        }
        uint32_t h, l;
        cvt2(v0, v1, h, l);
        int col = tp ^ ((n >> 3) & 3);
        Xhi[n * PSTR + col] = h;
        Xlo[n * PSTR + col] = l;
    }
    __syncthreads();

    for (int tile = tstart; tile < tend; tile++) {
        const int ij0 = tile * 128;

        // ---- AV planes ----
        {
            const int tp = tid & 31;
            const int r0 = tid >> 5;
            const int t0 = 2 * tp;
#pragma unroll 4
            for (int it = 0; it < 16; it++) {
                int ijl = it * 8 + r0;
                int ij  = ij0 + ijl;
                float v0 = 0.f, v1 = 0.f;
                if (ij < NIJ) {
                    int i = ij / 49;
                    int j = ij - i * 49;
                    float a0 = i ? aud[t0 * 49 + (i - 1)] : 1.f;
                    float a1 = i ? aud[(t0 + 1) * 49 + (i - 1)] : 1.f;
                    float w0 = j ? vid[t0 * 49 + (j - 1)] : 1.f;
                    float w1 = j ? vid[(t0 + 1) * 49 + (j - 1)] : 1.f;
                    v0 = a0 * w0;
                    v1 = a1 * w1;
                }
                uint32_t h, l;
                cvt2(v0, v1, h, l);
                Ahi[ijl * PSTR + tp] = h;
                Alo[ijl * PSTR + tp] = l;
            }
        }
        __syncthreads();

        // ---- 3-combo HMMA, K=64 ----
        float acc[4][4][4];
#pragma unroll
        for (int mt = 0; mt < 4; mt++)
#pragma unroll
            for (int nt = 0; nt < 4; nt++)
#pragma unroll
                for (int r = 0; r < 4; r++) acc[mt][nt][r] = 0.f;

#pragma unroll
        for (int ks = 0; ks < 4; ks++) {
            const int kp0 = ks * 8;
            uint32_t bh[4][2], bl[4][2];
#pragma unroll
            for (int nt = 0; nt < 4; nt++) {
                int n  = nbase + nt * 8 + g;
                int cB = (n >> 3) & 3;
                const uint32_t* ph = &Xhi[n * PSTR + kp0 + (tg ^ cB)];
                const uint32_t* pl = &Xlo[n * PSTR + kp0 + (tg ^ cB)];
                bh[nt][0] = ph[0]; bh[nt][1] = ph[4];
                bl[nt][0] = pl[0]; bl[nt][1] = pl[4];
            }
#pragma unroll
            for (int mt = 0; mt < 4; mt++) {
                const int r = mbase + mt * 16 + g;
                const uint32_t* ph = &Ahi[r * PSTR + kp0 + tg];
                const uint32_t* pl = &Alo[r * PSTR + kp0 + tg];
                uint32_t ah[4], al[4];
                ah[0] = ph[0]; ah[1] = ph[8 * PSTR]; ah[2] = ph[4]; ah[3] = ph[8 * PSTR + 4];
                al[0] = pl[0]; al[1] = pl[8 * PSTR]; al[2] = pl[4]; al[3] = pl[8 * PSTR + 4];
#pragma unroll
                for (int nt = 0; nt < 4; nt++) {
                    mma_bf16(acc[mt][nt], ah, bh[nt]);
                    mma_bf16(acc[mt][nt], ah, bl[nt]);
                    mma_bf16(acc[mt][nt], al, bh[nt]);
                }
            }
        }
        __syncthreads();   // all fragment LDS done before staging overwrite

        const int nrows = (NIJ - ij0 < 128) ? (NIJ - ij0) : 128;
        const int nw = nrows * 49;
        const size_t gbase = (size_t)b * FROWP + (size_t)ij0 * 49;

        // ---- pass 1: hi plane ----
#pragma unroll
        for (int mt = 0; mt < 4; mt++) {
            int row = mbase + mt * 16 + g;
#pragma unroll
            for (int nt = 0; nt < 4; nt++) {
                int col = nbase + nt * 8 + 2 * tg;
                if (col > 96) continue;
                int pr = col >> 1;
                stg[row * 49 + pr]       = cvthi(acc[mt][nt][0], acc[mt][nt][1]);
                stg[(row + 8) * 49 + pr] = cvthi(acc[mt][nt][2], acc[mt][nt][3]);
            }
        }
        __syncthreads();
        for (int idx = tid; idx < nw; idx += 256) g_Fhi[gbase + idx] = stg[idx];
        __syncthreads();

        // ---- pass 2: lo plane ----
#pragma unroll
        for (int mt = 0; mt < 4; mt++) {
            int row = mbase + mt * 16 + g;
#pragma unroll
            for (int nt = 0; nt < 4; nt++) {
                int col = nbase + nt * 8 + 2 * tg;
                if (col > 96) continue;
                int pr = col >> 1;
                uint32_t h, l;
                cvt2(acc[mt][nt][0], acc[mt][nt][1], h, l);
                stg[row * 49 + pr] = l;
                cvt2(acc[mt][nt][2], acc[mt][nt][3], h, l);
                stg[(row + 8) * 49 + pr] = l;
            }
        }
        __syncthreads();
        for (int idx = tid; idx < nw; idx += 256) g_Flo[gbase + idx] = stg[idx];
        __syncthreads();
    }
}

// ---------------------------------------------------------------------------
// Stage 2: split-K HMMA GEMM. grid NSPLIT, block 256.
static constexpr int S2_AHI = 0;
static constexpr int S2_ALO = 128 * PSTR;
static constexpr int S2_BHI = 2 * 128 * PSTR;
static constexpr int S2_BLO = 3 * 128 * PSTR;
static constexpr int S2_WORDS = 4 * 128 * PSTR;
static constexpr int S2_BYTES = S2_WORDS * 4;     // 73728

__global__ __launch_bounds__(256, 2)
void k_gemm_mma(const float* __restrict__ W1) {
    extern __shared__ uint32_t smw[];
    uint32_t* Ahi = smw + S2_AHI;
    uint32_t* Alo = smw + S2_ALO;
    uint32_t* Bhi = smw + S2_BHI;
    uint32_t* Blo = smw + S2_BLO;
    const uint32_t smb = smem_u32(smw);

    const int tid = threadIdx.x;
    const int wid = tid >> 5;
    const int lid = tid & 31;
    const int g   = lid >> 2;
    const int tg  = lid & 3;
    const int mbase = (wid >> 2) * 64;
    const int nbase = (wid & 3) * 32;

    float acc[4][4][4];
#pragma unroll
    for (int mt = 0; mt < 4; mt++)
#pragma unroll
        for (int nt = 0; nt < 4; nt++)
#pragma unroll
            for (int r = 0; r < 4; r++) acc[mt][nt][r] = 0.f;

    for (int c = blockIdx.x; c < NCHUNK2; c += NSPLIT) {
        const uint32_t kp_base = (uint32_t)c * KPC;
        __syncthreads();   // prev fragment LDS done

        // ---- A prefetch: cp.async raw plane copies ----
#pragma unroll
        for (int it = 0; it < 4; it++) {
            int idx = it * 256 + tid;
            int row = idx >> 3;
            int q4  = (idx & 7) * 4;
            CPA16(smb + (uint32_t)(S2_AHI + row * PSTR + q4) * 4,
                  &g_Fhi[(size_t)row * FROWP + kp_base + q4]);
        }
#pragma unroll
        for (int it = 0; it < 4; it++) {
            int idx = it * 256 + tid;
            int row = idx >> 3;
            int q4  = (idx & 7) * 4;
            CPA16(smb + (uint32_t)(S2_ALO + row * PSTR + q4) * 4,
                  &g_Flo[(size_t)row * FROWP + kp_base + q4]);
        }
        asm volatile("cp.async.commit_group;");

        // ---- B stage: cheap index math (one div per chunk) ----
        {
            const uint32_t flat0 = kp_base * 2u;
            const uint32_t ij_s  = flat0 / KXP;
            const int      rem   = (int)(flat0 - ij_s * KXP);
#pragma unroll
            for (int it = 0; it < 16; it++) {
                int kp = it * 2 + (tid >> 7);
                int p  = tid & 127;
                int loc  = rem + 2 * kp;           // 0..160
                int a0i  = (loc >= KXP);
                int cc0  = loc - (a0i ? KXP : 0);
                int ij0q = (int)ij_s + a0i;
                int loc1 = loc + 1;
                int a1i  = (loc1 >= KXP);
                int cc1  = loc1 - (a1i ? KXP : 0);
                int ij1q = (int)ij_s + a1i;
                float w0 = 0.f, w1 = 0.f;
                if (ij0q < NIJ && cc0 < KX)
                    w0 = W1[(size_t)(ij0q * KX + cc0) * PF + p];
                if (ij1q < NIJ && cc1 < KX)
                    w1 = W1[(size_t)(ij1q * KX + cc1) * PF + p];
                uint32_t h, l;
                cvt2(w0, w1, h, l);
                int col = kp ^ ((p >> 3) & 3);
                Bhi[p * PSTR + col] = h;
                Blo[p * PSTR + col] = l;
            }
        }
        asm volatile("cp.async.wait_group 0;");
        __syncthreads();

        // ---- compute ----
#pragma unroll
        for (int ks = 0; ks < 4; ks++) {
            const int kp0 = ks * 8;
            uint32_t bh[4][2], bl[4][2];
#pragma unroll
            for (int nt = 0; nt < 4; nt++) {
                int n  = nbase + nt * 8 + g;
                int cB = (n >> 3) & 3;
                const uint32_t* ph = &Bhi[n * PSTR + kp0 + (tg ^ cB)];
                const uint32_t* pl = &Blo[n * PSTR + kp0 + (tg ^ cB)];
                bh[nt][0] = ph[0]; bh[nt][1] = ph[4];
                bl[nt][0] = pl[0]; bl[nt][1] = pl[4];
            }
#pragma unroll
            for (int mt = 0; mt < 4; mt++) {
                const int r = mbase + mt * 16 + g;
                const uint32_t* ph = &Ahi[r * PSTR + kp0 + tg];
                const uint32_t* pl = &Alo[r * PSTR + kp0 + tg];
                uint32_t ah[4], al[4];
                ah[0] = ph[0]; ah[1] = ph[8 * PSTR]; ah[2] = ph[4]; ah[3] = ph[8 * PSTR + 4];
                al[0] = pl[0]; al[1] = pl[8 * PSTR]; al[2] = pl[4]; al[3] = pl[8 * PSTR + 4];
#pragma unroll
                for (int nt = 0; nt < 4; nt++) {
                    mma_bf16(acc[mt][nt], ah, bh[nt]);
                    mma_bf16(acc[mt][nt], ah, bl[nt]);
                    mma_bf16(acc[mt][nt], al, bh[nt]);
                }
            }
        }
    }

    float* part = &g_part[(size_t)blockIdx.x * (B_ * PF)];
#pragma unroll
    for (int mt = 0; mt < 4; mt++) {
        int row = mbase + mt * 16 + g;
#pragma unroll
        for (int nt = 0; nt < 4; nt++) {
            int col = nbase + nt * 8 + 2 * tg;
            *reinterpret_cast<float2*>(&part[(size_t)row * PF + col]) =
                make_float2(acc[mt][nt][0], acc[mt][nt][1]);
            *reinterpret_cast<float2*>(&part[(size_t)(row + 8) * PF + col]) =
                make_float2(acc[mt][nt][2], acc[mt][nt][3]);
        }
    }
}

// ---------------------------------------------------------------------------
__global__ void k_finish(const float* __restrict__ b1, const float* __restrict__ W2,
                         const float* __restrict__ b2, const float* __restrict__ W3,
                         const float* __restrict__ b3, float* __restrict__ out) {
    __shared__ float h1s[PF];
    __shared__ float red[PF];
    const int b = blockIdx.x;
    const int q = threadIdx.x;

    float s0 = 0.f, s1 = 0.f, s2 = 0.f, s3 = 0.f;
    const size_t off = (size_t)b * PF + q;
#pragma unroll 4
    for (int c = 0; c < NSPLIT; c += 4) {
        s0 += g_part[(size_t)(c + 0) * (B_ * PF) + off];
        s1 += g_part[(size_t)(c + 1) * (B_ * PF) + off];
        s2 += g_part[(size_t)(c + 2) * (B_ * PF) + off];
        s3 += g_part[(size_t)(c + 3) * (B_ * PF) + off];
    }
    float h1 = (s0 + s1) + (s2 + s3) + b1[q];
    h1s[q] = fmaxf(h1, 0.f);
    __syncthreads();

    float a0 = b2[q], a1 = 0.f, a2 = 0.f, a3 = 0.f;
#pragma unroll 8
    for (int p = 0; p < PF; p += 4) {
        a0 = fmaf(h1s[p + 0], W2[(p + 0) * PF + q], a0);
        a1 = fmaf(h1s[p + 1], W2[(p + 1) * PF + q], a1);
        a2 = fmaf(h1s[p + 2], W2[(p + 2) * PF + q], a2);
        a3 = fmaf(h1s[p + 3], W2[(p + 3) * PF + q], a3);
    }
    float h2 = fmaxf((a0 + a1) + (a2 + a3), 0.f);

    red[q] = h2 * W3[q];
    __syncthreads();
    for (int s = 64; s > 0; s >>= 1) {
        if (q < s) red[q] += red[q + s];
        __syncthreads();
    }
    if (q == 0) {
        float z = red[0] + b3[0];
        out[b] = 6.f / (1.f + expf(-z)) - 3.f;
    }
}

// ---------------------------------------------------------------------------
extern "C" void kernel_launch(void* const* d_in, const int* in_sizes, int n_in,
                              void* d_out, int out_size) {
    const float* audio = (const float*)d_in[0];
    const float* video = (const float*)d_in[1];
    const float* text  = (const float*)d_in[2];
    const float* W1    = (const float*)d_in[3];
    const float* b1    = (const float*)d_in[4];
    const float* W2    = (const float*)d_in[5];
    const float* b2    = (const float*)d_in[6];
    const float* W3    = (const float*)d_in[7];
    const float* b3    = (const float*)d_in[8];
    float* out = (float*)d_out;

    cudaFuncSetAttribute(k_build_F, cudaFuncAttributeMaxDynamicSharedMemorySize, S1_BYTES);
    cudaFuncSetAttribute(k_gemm_mma, cudaFuncAttributeMaxDynamicSharedMemorySize, S2_BYTES);

    k_build_F<<<dim3(2, 128), 256, S1_BYTES>>>(audio, video, text);
    k_gemm_mma<<<NSPLIT, 256, S2_BYTES>>>(W1);
    k_finish<<<128, 128>>>(b1, W2, b2, W3, b3, out);
}

// round 12
// speedup vs baseline: 2.9693x; 1.0760x over previous
#include <cuda_runtime.h>
#include <cuda_bf16.h>
#include <cstdint>

// ---------------------------------------------------------------------------
// T2FN on GB300 — hi/lo bf16 planes + ldmatrix fragment loads:
//  Stage 1 (k_build_F): per-b persistent CTA, HMMA GEMM AV@X, coalesced F IO
//  Stage 2 (k_gemm_mma): h1_pre = F @ W1, split-K, cp.async A, k-major B + trans LDSM
//  Stage 3 (k_finish):   reduce partials + MLP tail
// ---------------------------------------------------------------------------

#define B_    128
#define T_    64
#define ADIM  48
#define XDIM  96
#define PF    128
#define NIJ   2401        // 49*49
#define KX    97          // X+1
#define KXP   98
#define KPC   32          // pairs per chunk (64 flat k)
#define NCHUNK2 3677
#define FROWP 117664u     // padded pairs per b (3677*32)
#define NSPLIT 296

__device__ uint32_t g_Fhi[(size_t)B_ * FROWP];
__device__ uint32_t g_Flo[(size_t)B_ * FROWP];
__device__ float    g_part[(size_t)NSPLIT * B_ * PF];

static __device__ __forceinline__ uint32_t cvthi(float v0, float v1) {
    uint32_t h;
    asm("cvt.rn.bf16x2.f32 %0, %1, %2;" : "=r"(h) : "f"(v1), "f"(v0));
    return h;
}
static __device__ __forceinline__ void cvt2(float v0, float v1, uint32_t& h, uint32_t& l) {
    uint32_t hh = cvthi(v0, v1);
    float h0 = __uint_as_float(hh << 16);
    float h1 = __uint_as_float(hh & 0xFFFF0000u);
    float r0 = v0 - h0, r1 = v1 - h1;
    asm("cvt.rn.bf16x2.f32 %0, %1, %2;" : "=r"(l) : "f"(r1), "f"(r0));
    h = hh;
}
static __device__ __forceinline__ uint32_t smem_u32(const void* p) {
    uint32_t a;
    asm("{ .reg .u64 t; cvta.to.shared.u64 t, %1; cvt.u32.u64 %0, t; }" : "=r"(a) : "l"(p));
    return a;
}
#define CPA16(dst, src) \
    asm volatile("cp.async.cg.shared.global [%0], [%1], 16;" :: "r"(dst), "l"(src))

static __device__ __forceinline__ void mma_bf16(float* d, const uint32_t* a,
                                                const uint32_t* b) {
    asm volatile(
        "mma.sync.aligned.m16n8k16.row.col.f32.bf16.bf16.f32 "
        "{%0,%1,%2,%3}, {%4,%5,%6,%7}, {%8,%9}, {%0,%1,%2,%3};"
        : "+f"(d[0]), "+f"(d[1]), "+f"(d[2]), "+f"(d[3])
        : "r"(a[0]), "r"(a[1]), "r"(a[2]), "r"(a[3]), "r"(b[0]), "r"(b[1]));
}
static __device__ __forceinline__ void ldsm4(uint32_t* r, uint32_t addr) {
    asm volatile("ldmatrix.sync.aligned.m8n8.x4.shared.b16 {%0,%1,%2,%3}, [%4];"
                 : "=r"(r[0]), "=r"(r[1]), "=r"(r[2]), "=r"(r[3]) : "r"(addr));
}
static __device__ __forceinline__ void ldsm4t(uint32_t* r, uint32_t addr) {
    asm volatile("ldmatrix.sync.aligned.m8n8.x4.trans.shared.b16 {%0,%1,%2,%3}, [%4];"
                 : "=r"(r[0]), "=r"(r[1]), "=r"(r[2]), "=r"(r[3]) : "r"(addr));
}

static constexpr int PSTR = 36;   // A-plane row stride (u32 words; k-pair major)
static constexpr int XSTR = 68;   // B-plane row stride (u32 words; [k][n] bf16, 128 n)

// ---------------------------------------------------------------------------
// Stage 1 smem (words):
static constexpr int S1_ALO = 4608;                  // Ahi @0 (128*36)
static constexpr int S1_XHI = 9216;                  // Xhi [64 t][68]
static constexpr int S1_XLO = S1_XHI + 64 * XSTR;    // 13568
static constexpr int S1_AUD = S1_XLO + 64 * XSTR;    // 17920
static constexpr int S1_VID = S1_AUD + T_ * 49;      // 21056
static constexpr int S1_WORDS = S1_VID + T_ * 49;    // 24192
static constexpr int S1_BYTES = S1_WORDS * 4;        // 96768

__global__ __launch_bounds__(256, 2)
void k_build_F(const float* __restrict__ audio,
               const float* __restrict__ video,
               const float* __restrict__ text) {
    extern __shared__ uint32_t smw[];
    uint32_t* Ahi = smw;
    uint32_t* Alo = smw + S1_ALO;
    uint32_t* Xhi = smw + S1_XHI;
    uint32_t* Xlo = smw + S1_XLO;
    uint32_t* stg = smw;                 // epilogue overlay (6272 words <= 9216)
    float* aud = reinterpret_cast<float*>(smw + S1_AUD);
    float* vid = reinterpret_cast<float*>(smw + S1_VID);

    const int b      = blockIdx.y;
    const int tstart = blockIdx.x ? 10 : 0;
    const int tend   = blockIdx.x ? 19 : 10;
    const int tid = threadIdx.x;
    const int wid = tid >> 5;
    const int lid = tid & 31;
    const int g   = lid >> 2;
    const int tg  = lid & 3;
    const int mbase = (wid >> 2) * 64;
    const int nbase = (wid & 3) * 32;

    // ---- one-time staging: aud/vid + X planes ([t][n] bf16) ----
#pragma unroll 3
    for (int idx = tid; idx < T_ * ADIM; idx += 256) {
        int t = idx / ADIM, c = idx - t * ADIM;
        aud[t * 49 + c] = audio[(size_t)b * (T_ * ADIM) + idx];
        vid[t * 49 + c] = video[(size_t)b * (T_ * ADIM) + idx];
    }
#pragma unroll
    for (int r = 0; r < 8; r++) {
        int t = wid * 8 + r;
        const float* trow = &text[((size_t)b * T_ + t) * XDIM];
#pragma unroll
        for (int h = 0; h < 2; h++) {
            int c  = lid + h * 32;        // word = n-pair (2c, 2c+1)
            int n0 = 2 * c, n1 = 2 * c + 1;
            float v0 = (n0 == 0) ? 1.f : ((n0 < KX) ? trow[n0 - 1] : 0.f);
            float v1 = (n1 < KX) ? trow[n1 - 1] : 0.f;
            uint32_t hw, lw;
            cvt2(v0, v1, hw, lw);
            Xhi[t * XSTR + c] = hw;
            Xlo[t * XSTR + c] = lw;
        }
    }
    __syncthreads();

    // per-warp ldmatrix base offsets
    const uint32_t aOff = (uint32_t)(mbase + (lid & 15)) * (PSTR * 4) + (lid >> 4) * 16;
    const uint32_t aAhi = smem_u32(Ahi) + aOff;
    const uint32_t aAlo = smem_u32(Alo) + aOff;
    const uint32_t bOff = (uint32_t)(lid & 15) * (XSTR * 4) + (uint32_t)(nbase + (lid >> 4) * 8) * 2;
    const uint32_t aXhi = smem_u32(Xhi) + bOff;
    const uint32_t aXlo = smem_u32(Xlo) + bOff;

    for (int tile = tstart; tile < tend; tile++) {
        const int ij0 = tile * 128;

        // ---- AV planes [ijl][t-pair] ----
        {
            const int tp = tid & 31;
            const int r0 = tid >> 5;
            const int t0 = 2 * tp;
#pragma unroll 4
            for (int it = 0; it < 16; it++) {
                int ijl = it * 8 + r0;
                int ij  = ij0 + ijl;
                float v0 = 0.f, v1 = 0.f;
                if (ij < NIJ) {
                    int i = ij / 49;
                    int j = ij - i * 49;
                    float a0 = i ? aud[t0 * 49 + (i - 1)] : 1.f;
                    float a1 = i ? aud[(t0 + 1) * 49 + (i - 1)] : 1.f;
                    float w0 = j ? vid[t0 * 49 + (j - 1)] : 1.f;
                    float w1 = j ? vid[(t0 + 1) * 49 + (j - 1)] : 1.f;
                    v0 = a0 * w0;
                    v1 = a1 * w1;
                }
                uint32_t h, l;
                cvt2(v0, v1, h, l);
                Ahi[ijl * PSTR + tp] = h;
                Alo[ijl * PSTR + tp] = l;
            }
        }
        __syncthreads();

        // ---- 3-combo HMMA, K=64 ----
        float acc[4][4][4];
#pragma unroll
        for (int mt = 0; mt < 4; mt++)
#pragma unroll
            for (int nt = 0; nt < 4; nt++)
#pragma unroll
                for (int r = 0; r < 4; r++) acc[mt][nt][r] = 0.f;

#pragma unroll
        for (int ks = 0; ks < 4; ks++) {
            uint32_t bh[8], bl[8];
            const uint32_t bk = (uint32_t)ks * 16 * (XSTR * 4);
            ldsm4t(bh + 0, aXhi + bk);
            ldsm4t(bh + 4, aXhi + bk + 32);
            ldsm4t(bl + 0, aXlo + bk);
            ldsm4t(bl + 4, aXlo + bk + 32);
#pragma unroll
            for (int mt = 0; mt < 4; mt++) {
                const uint32_t am = (uint32_t)mt * 16 * (PSTR * 4) + (uint32_t)ks * 32;
                uint32_t ah[4], al[4];
                ldsm4(ah, aAhi + am);
                ldsm4(al, aAlo + am);
#pragma unroll
                for (int nt = 0; nt < 4; nt++) {
                    mma_bf16(acc[mt][nt], ah, &bh[2 * nt]);
                    mma_bf16(acc[mt][nt], ah, &bl[2 * nt]);
                    mma_bf16(acc[mt][nt], al, &bh[2 * nt]);
                }
            }
        }
        __syncthreads();   // fragment loads done before staging overwrite

        const int nrows = (NIJ - ij0 < 128) ? (NIJ - ij0) : 128;
        const int nw = nrows * 49;
        const size_t gbase = (size_t)b * FROWP + (size_t)ij0 * 49;

        // ---- pass 1: hi plane ----
#pragma unroll
        for (int mt = 0; mt < 4; mt++) {
            int row = mbase + mt * 16 + g;
#pragma unroll
            for (int nt = 0; nt < 4; nt++) {
                int col = nbase + nt * 8 + 2 * tg;
                if (col > 96) continue;
                int pr = col >> 1;
                stg[row * 49 + pr]       = cvthi(acc[mt][nt][0], acc[mt][nt][1]);
                stg[(row + 8) * 49 + pr] = cvthi(acc[mt][nt][2], acc[mt][nt][3]);
            }
        }
        __syncthreads();
        for (int idx = tid; idx < nw; idx += 256) g_Fhi[gbase + idx] = stg[idx];
        __syncthreads();

        // ---- pass 2: lo plane ----
#pragma unroll
        for (int mt = 0; mt < 4; mt++) {
            int row = mbase + mt * 16 + g;
#pragma unroll
            for (int nt = 0; nt < 4; nt++) {
                int col = nbase + nt * 8 + 2 * tg;
                if (col > 96) continue;
                int pr = col >> 1;
                uint32_t h, l;
                cvt2(acc[mt][nt][0], acc[mt][nt][1], h, l);
                stg[row * 49 + pr] = l;
                cvt2(acc[mt][nt][2], acc[mt][nt][3], h, l);
                stg[(row + 8) * 49 + pr] = l;
            }
        }
        __syncthreads();
        for (int idx = tid; idx < nw; idx += 256) g_Flo[gbase + idx] = stg[idx];
        __syncthreads();
    }
}

// ---------------------------------------------------------------------------
// Stage 2: split-K HMMA GEMM. grid NSPLIT, block 256.
static constexpr int S2_ALO = 4608;                  // Ahi @0
static constexpr int S2_BHI = 9216;                  // Bhi [64 k][68] bf16[k][n]
static constexpr int S2_BLO = S2_BHI + 64 * XSTR;    // 13568
static constexpr int S2_WORDS = S2_BLO + 64 * XSTR;  // 17920
static constexpr int S2_BYTES = S2_WORDS * 4;        // 71680

__global__ __launch_bounds__(256, 2)
void k_gemm_mma(const float* __restrict__ W1) {
    extern __shared__ uint32_t smw[];
    uint32_t* Ahi = smw;
    uint32_t* Alo = smw + S2_ALO;
    uint32_t* Bhi = smw + S2_BHI;
    uint32_t* Blo = smw + S2_BLO;
    const uint32_t smb = smem_u32(smw);

    const int tid = threadIdx.x;
    const int wid = tid >> 5;
    const int lid = tid & 31;
    const int mbase = (wid >> 2) * 64;
    const int nbase = (wid & 3) * 32;
    const int g  = lid >> 2;
    const int tg = lid & 3;

    const uint32_t aOff = (uint32_t)(mbase + (lid & 15)) * (PSTR * 4) + (lid >> 4) * 16;
    const uint32_t aAhi = smb + aOff;
    const uint32_t aAlo = smb + (uint32_t)S2_ALO * 4 + aOff;
    const uint32_t bOff = (uint32_t)(lid & 15) * (XSTR * 4) + (uint32_t)(nbase + (lid >> 4) * 8) * 2;
    const uint32_t aBhi = smb + (uint32_t)S2_BHI * 4 + bOff;
    const uint32_t aBlo = smb + (uint32_t)S2_BLO * 4 + bOff;

    float acc[4][4][4];
#pragma unroll
    for (int mt = 0; mt < 4; mt++)
#pragma unroll
        for (int nt = 0; nt < 4; nt++)
#pragma unroll
            for (int r = 0; r < 4; r++) acc[mt][nt][r] = 0.f;

    for (int c = blockIdx.x; c < NCHUNK2; c += NSPLIT) {
        const uint32_t kp_base = (uint32_t)c * KPC;
        __syncthreads();   // prev fragment loads done

        // ---- A prefetch: cp.async raw plane copies ----
#pragma unroll
        for (int it = 0; it < 4; it++) {
            int idx = it * 256 + tid;
            int row = idx >> 3;
            int q4  = (idx & 7) * 4;
            CPA16(smb + (uint32_t)(row * PSTR + q4) * 4,
                  &g_Fhi[(size_t)row * FROWP + kp_base + q4]);
        }
#pragma unroll
        for (int it = 0; it < 4; it++) {
            int idx = it * 256 + tid;
            int row = idx >> 3;
            int q4  = (idx & 7) * 4;
            CPA16(smb + (uint32_t)(S2_ALO + row * PSTR + q4) * 4,
                  &g_Flo[(size_t)row * FROWP + kp_base + q4]);
        }
        asm volatile("cp.async.commit_group;");

        // ---- B stage: W1 -> [k][n] bf16 planes (coalesced float2, no transpose) ----
        {
            const uint32_t flat0 = kp_base * 2u;
            const uint32_t ij_s  = flat0 / KXP;
            const int      rem   = (int)(flat0 - ij_s * KXP);
#pragma unroll
            for (int r = 0; r < 8; r++) {
                int kr  = wid * 8 + r;
                int loc = rem + kr;
                int add = (loc >= KXP);
                int cc  = loc - (add ? KXP : 0);
                uint32_t ijq = ij_s + (uint32_t)add;
                bool rv = (cc < KX) && (ijq < NIJ);
                const float* wrow = W1 + ((size_t)ijq * KX + cc) * PF;
#pragma unroll
                for (int h = 0; h < 2; h++) {
                    int cw = lid + h * 32;
                    float2 w = rv ? *reinterpret_cast<const float2*>(wrow + 2 * cw)
                                  : make_float2(0.f, 0.f);
                    uint32_t hw, lw;
                    cvt2(w.x, w.y, hw, lw);
                    Bhi[kr * XSTR + cw] = hw;
                    Blo[kr * XSTR + cw] = lw;
                }
            }
        }
        asm volatile("cp.async.wait_group 0;");
        __syncthreads();

        // ---- compute: 4 ksteps x 3 combos ----
#pragma unroll
        for (int ks = 0; ks < 4; ks++) {
            uint32_t bh[8], bl[8];
            const uint32_t bk = (uint32_t)ks * 16 * (XSTR * 4);
            ldsm4t(bh + 0, aBhi + bk);
            ldsm4t(bh + 4, aBhi + bk + 32);
            ldsm4t(bl + 0, aBlo + bk);
            ldsm4t(bl + 4, aBlo + bk + 32);
#pragma unroll
            for (int mt = 0; mt < 4; mt++) {
                const uint32_t am = (uint32_t)mt * 16 * (PSTR * 4) + (uint32_t)ks * 32;
                uint32_t ah[4], al[4];
                ldsm4(ah, aAhi + am);
                ldsm4(al, aAlo + am);
#pragma unroll
                for (int nt = 0; nt < 4; nt++) {
                    mma_bf16(acc[mt][nt], ah, &bh[2 * nt]);
                    mma_bf16(acc[mt][nt], ah, &bl[2 * nt]);
                    mma_bf16(acc[mt][nt], al, &bh[2 * nt]);
                }
            }
        }
    }

    float* part = &g_part[(size_t)blockIdx.x * (B_ * PF)];
#pragma unroll
    for (int mt = 0; mt < 4; mt++) {
        int row = mbase + mt * 16 + g;
#pragma unroll
        for (int nt = 0; nt < 4; nt++) {
            int col = nbase + nt * 8 + 2 * tg;
            *reinterpret_cast<float2*>(&part[(size_t)row * PF + col]) =
                make_float2(acc[mt][nt][0], acc[mt][nt][1]);
            *reinterpret_cast<float2*>(&part[(size_t)(row + 8) * PF + col]) =
                make_float2(acc[mt][nt][2], acc[mt][nt][3]);
        }
    }
}

// ---------------------------------------------------------------------------
__global__ void k_finish(const float* __restrict__ b1, const float* __restrict__ W2,
                         const float* __restrict__ b2, const float* __restrict__ W3,
                         const float* __restrict__ b3, float* __restrict__ out) {
    __shared__ float h1s[PF];
    __shared__ float red[PF];
    const int b = blockIdx.x;
    const int q = threadIdx.x;

    float s0 = 0.f, s1 = 0.f, s2 = 0.f, s3 = 0.f;
    const size_t off = (size_t)b * PF + q;
#pragma unroll 4
    for (int c = 0; c < NSPLIT; c += 4) {
        s0 += g_part[(size_t)(c + 0) * (B_ * PF) + off];
        s1 += g_part[(size_t)(c + 1) * (B_ * PF) + off];
        s2 += g_part[(size_t)(c + 2) * (B_ * PF) + off];
        s3 += g_part[(size_t)(c + 3) * (B_ * PF) + off];
    }
    float h1 = (s0 + s1) + (s2 + s3) + b1[q];
    h1s[q] = fmaxf(h1, 0.f);
    __syncthreads();

    float a0 = b2[q], a1 = 0.f, a2 = 0.f, a3 = 0.f;
#pragma unroll 8
    for (int p = 0; p < PF; p += 4) {
        a0 = fmaf(h1s[p + 0], W2[(p + 0) * PF + q], a0);
        a1 = fmaf(h1s[p + 1], W2[(p + 1) * PF + q], a1);
        a2 = fmaf(h1s[p + 2], W2[(p + 2) * PF + q], a2);
        a3 = fmaf(h1s[p + 3], W2[(p + 3) * PF + q], a3);
    }
    float h2 = fmaxf((a0 + a1) + (a2 + a3), 0.f);

    red[q] = h2 * W3[q];
    __syncthreads();
    for (int s = 64; s > 0; s >>= 1) {
        if (q < s) red[q] += red[q + s];
        __syncthreads();
    }
    if (q == 0) {
        float z = red[0] + b3[0];
        out[b] = 6.f / (1.f + expf(-z)) - 3.f;
    }
}

// ---------------------------------------------------------------------------
extern "C" void kernel_launch(void* const* d_in, const int* in_sizes, int n_in,
                              void* d_out, int out_size) {
    const float* audio = (const float*)d_in[0];
    const float* video = (const float*)d_in[1];
    const float* text  = (const float*)d_in[2];
    const float* W1    = (const float*)d_in[3];
    const float* b1    = (const float*)d_in[4];
    const float* W2    = (const float*)d_in[5];
    const float* b2    = (const float*)d_in[6];
    const float* W3    = (const float*)d_in[7];
    const float* b3    = (const float*)d_in[8];
    float* out = (float*)d_out;

    cudaFuncSetAttribute(k_build_F, cudaFuncAttributeMaxDynamicSharedMemorySize, S1_BYTES);
    cudaFuncSetAttribute(k_gemm_mma, cudaFuncAttributeMaxDynamicSharedMemorySize, S2_BYTES);

    k_build_F<<<dim3(2, 128), 256, S1_BYTES>>>(audio, video, text);
    k_gemm_mma<<<NSPLIT, 256, S2_BYTES>>>(W1);
    k_finish<<<128, 128>>>(b1, W2, b2, W3, b3, out);
}